// round 14
// baseline (speedup 1.0000x reference)
#include <cuda_runtime.h>
#include <cuda_bf16.h>
#include <cuda_fp16.h>
#include <cstdint>
#include <cstddef>

// ---------------- problem constants ----------------
#define BATCH   64
#define HW_     256
#define NTOK    256
#define IMG_CH  1024
#define TEXT_CH 768
#define FQK     512
#define M_FLAT  (BATCH * HW_)                       // 16384
#define O_ELEMS ((size_t)M_FLAT * IMG_CH)           // 16,777,216

// ---------------- scratch ----------------
#define DECLB(name, n) __device__ __align__(256) __nv_bfloat16 name[(size_t)(n)]
#define DECLH(name, n) __device__ __align__(256) __half name[(size_t)(n)]
DECLB(g_x1h, (size_t)M_FLAT * IMG_CH);  DECLB(g_x1l, (size_t)M_FLAT * IMG_CH);
DECLB(g_x2h, (size_t)M_FLAT * TEXT_CH); DECLB(g_x2l, (size_t)M_FLAT * TEXT_CH);
DECLB(g_wqh, (size_t)FQK * IMG_CH);     DECLB(g_wql, (size_t)FQK * IMG_CH);     // Wq^T [512,1024]
DECLB(g_wkh, (size_t)FQK * TEXT_CH);    DECLB(g_wkl, (size_t)FQK * TEXT_CH);    // Wk^T [512,768]
DECLB(g_wvh, (size_t)TEXT_CH * IMG_CH); DECLB(g_wvl, (size_t)TEXT_CH * IMG_CH); // Wv PLAIN split [768,1024]
DECLB(g_woh, (size_t)IMG_CH * IMG_CH);  DECLB(g_wol, (size_t)IMG_CH * IMG_CH);  // Wo^T [1024,1024]
DECLB(g_qh,  (size_t)M_FLAT * FQK);     DECLB(g_ql,  (size_t)M_FLAT * FQK);
DECLB(g_kh,  (size_t)M_FLAT * FQK);     DECLB(g_kl,  (size_t)M_FLAT * FQK);
// fp16 beta-path scratch (all SINGLE precision fp16)
DECLH(g_wvot16, (size_t)IMG_CH * TEXT_CH);            // (Wv.Wo)^T fp16 [1024,768]
DECLH(g_x2t16,  (size_t)BATCH * TEXT_CH * NTOK);      // x2^T fp16 per batch
DECLH(g_bt16,   (size_t)M_FLAT * NTOK);               // beta fp16
DECLH(g_bx16,   (size_t)M_FLAT * TEXT_CH);            // beta@x2 fp16
__device__ __align__(256) float g_rowsum[M_FLAT];     // masked rowsum of beta
__device__ __align__(256) float g_bvwo[IMG_CH];       // bv @ Wo

// ---------------- PTX helpers (baseline PTX only) ----------------
__device__ __forceinline__ uint32_t smem_u32(const void* p) {
    uint32_t a;
    asm("{ .reg .u64 t; cvta.to.shared.u64 t, %1; cvt.u32.u64 %0, t; }" : "=r"(a) : "l"(p));
    return a;
}
__device__ __forceinline__ void cpasync16(uint32_t dst, const void* src) {
    asm volatile("cp.async.cg.shared.global [%0], [%1], 16;" :: "r"(dst), "l"(src));
}
__device__ __forceinline__ void cp_commit() { asm volatile("cp.async.commit_group;" ::: "memory"); }
__device__ __forceinline__ void cp_wait1()  { asm volatile("cp.async.wait_group 1;" ::: "memory"); }

__device__ __forceinline__ void ldm4(uint32_t* r, uint32_t addr) {
    asm volatile("ldmatrix.sync.aligned.m8n8.x4.shared.b16 {%0,%1,%2,%3}, [%4];"
                 : "=r"(r[0]), "=r"(r[1]), "=r"(r[2]), "=r"(r[3]) : "r"(addr));
}
template<bool FP16>
__device__ __forceinline__ void mma16816t(float* d, const uint32_t* a, const uint32_t* b) {
    if constexpr (FP16)
        asm volatile("mma.sync.aligned.m16n8k16.row.col.f32.f16.f16.f32 "
                     "{%0,%1,%2,%3}, {%4,%5,%6,%7}, {%8,%9}, {%0,%1,%2,%3};"
                     : "+f"(d[0]), "+f"(d[1]), "+f"(d[2]), "+f"(d[3])
                     : "r"(a[0]), "r"(a[1]), "r"(a[2]), "r"(a[3]), "r"(b[0]), "r"(b[1]));
    else
        asm volatile("mma.sync.aligned.m16n8k16.row.col.f32.bf16.bf16.f32 "
                     "{%0,%1,%2,%3}, {%4,%5,%6,%7}, {%8,%9}, {%0,%1,%2,%3};"
                     : "+f"(d[0]), "+f"(d[1]), "+f"(d[2]), "+f"(d[3])
                     : "r"(a[0]), "r"(a[1]), "r"(a[2]), "r"(a[3]), "r"(b[0]), "r"(b[1]));
}
// SW64 swizzle for 64-byte rows (8-row atom), conflict-free for cp.async stores + ldmatrix
__device__ __forceinline__ uint32_t swz64(uint32_t off) { return off ^ ((off >> 3) & 0x30); }
__device__ __forceinline__ uint32_t pack_bf2(__nv_bfloat16 a, __nv_bfloat16 b) {
    return (uint32_t)__bfloat16_as_ushort(a) | ((uint32_t)__bfloat16_as_ushort(b) << 16);
}
__device__ __forceinline__ uint32_t pack_hf2(__half a, __half b) {
    return (uint32_t)__half_as_ushort(a) | ((uint32_t)__half_as_ushort(b) << 16);
}

// ---------------- prep kernels ----------------
__global__ void split_kernel(const float* __restrict__ in,
                             __nv_bfloat16* __restrict__ h,
                             __nv_bfloat16* __restrict__ l, int n4) {
    int i = blockIdx.x * blockDim.x + threadIdx.x;
    if (i >= n4) return;
    float4 v = ((const float4*)in)[i];
    __nv_bfloat16 h0 = __float2bfloat16(v.x), h1 = __float2bfloat16(v.y);
    __nv_bfloat16 h2 = __float2bfloat16(v.z), h3 = __float2bfloat16(v.w);
    __nv_bfloat16 l0 = __float2bfloat16(v.x - __bfloat162float(h0));
    __nv_bfloat16 l1 = __float2bfloat16(v.y - __bfloat162float(h1));
    __nv_bfloat16 l2 = __float2bfloat16(v.z - __bfloat162float(h2));
    __nv_bfloat16 l3 = __float2bfloat16(v.w - __bfloat162float(h3));
    ((uint2*)h)[i] = make_uint2(pack_bf2(h0, h1), pack_bf2(h2, h3));
    ((uint2*)l)[i] = make_uint2(pack_bf2(l0, l1), pack_bf2(l2, l3));
}

// W (R x C row-major) -> WT hi/lo (C x R row-major), bf16
__global__ void transpose_split_kernel(const float* __restrict__ W,
                                       __nv_bfloat16* __restrict__ Th,
                                       __nv_bfloat16* __restrict__ Tl,
                                       int R, int C) {
    __shared__ float t[32][33];
    int c0 = blockIdx.x * 32, r0 = blockIdx.y * 32;
    int x = threadIdx.x, y = threadIdx.y;          // (32, 8)
    #pragma unroll
    for (int i = 0; i < 32; i += 8)
        t[y + i][x] = W[(size_t)(r0 + y + i) * C + c0 + x];
    __syncthreads();
    #pragma unroll
    for (int i = 0; i < 32; i += 8) {
        float v = t[x][y + i];
        __nv_bfloat16 hb = __float2bfloat16(v);
        __nv_bfloat16 lb = __float2bfloat16(v - __bfloat162float(hb));
        size_t idx = (size_t)(c0 + y + i) * R + r0 + x;
        Th[idx] = hb;
        Tl[idx] = lb;
    }
}

// per batch float [R,C] -> fp16 single [C,R]
__global__ void transpose_f2h_kernel(const float* __restrict__ in,
                                     __half* __restrict__ out, int R, int C) {
    __shared__ float t[32][33];
    const int b = blockIdx.z;
    const int c0 = blockIdx.x * 32, r0 = blockIdx.y * 32;
    const int x = threadIdx.x, y = threadIdx.y;    // (32, 8)
    const size_t base = (size_t)b * R * C;
    #pragma unroll
    for (int i = 0; i < 32; i += 8)
        t[y + i][x] = in[base + (size_t)(r0 + y + i) * C + c0 + x];
    __syncthreads();
    #pragma unroll
    for (int i = 0; i < 32; i += 8)
        out[base + (size_t)(c0 + y + i) * R + r0 + x] = __float2half_rn(t[x][y + i]);
}

// bvwo[f] = sum_k bv[k] * Wo[k,f]
__global__ void bias_vo_kernel(const float* __restrict__ bv,
                               const float* __restrict__ Wo,
                               float* __restrict__ bvwo) {
    int f = blockIdx.x * blockDim.x + threadIdx.x;
    if (f >= IMG_CH) return;
    float s = 0.f;
    for (int k = 0; k < IMG_CH; ++k) s += bv[k] * Wo[(size_t)k * IMG_CH + f];
    bvwo[f] = s;
}

// ---------------- HMMA split GEMM (generic) ----------------
// TERMS==3 (bf16): C = AhBh + AhBl + AlBh. Tiles Ah|Al|Bh|Bl. occ 2.
// TERMS==1 (fp16): C = AB (both single). Tiles A|B. occ 3 (more warps to fill issue).
// A: [M,K] row-major, B: [N,K] row-major. BM=BN=128, BK=32, 3-stage cp.async ring.
// 128 threads (4 warps, 2x2 grid of 64x64 warp tiles). Term-major MMA order.
// EPI 1: hi/lo bf16 split out + bias.  EPI 2: fp32 + bias + rs[row]*b2[col].
// EPI 3: fp16 SINGLE out (Chi as __half*).
#define NST   3
#define TILEB (128 * 32 * 2)            // 8 KB per sub-tile

template<int EPI, bool FP16, int TERMS>
__global__ __launch_bounds__(128, (TERMS == 1) ? 3 : 2)
void hmma_gemm(const __nv_bfloat16* __restrict__ Ah, const __nv_bfloat16* __restrict__ Al,
               const __nv_bfloat16* __restrict__ Bh, const __nv_bfloat16* __restrict__ Bl,
               const float* __restrict__ bias,
               float* __restrict__ Cf,
               __nv_bfloat16* __restrict__ Chi, __nv_bfloat16* __restrict__ Clo,
               const float* __restrict__ rs, const float* __restrict__ b2,
               int N, int K, size_t sA, size_t sB, size_t sC)
{
    constexpr uint32_t NTILES = (TERMS == 3) ? 4 : 2;
    constexpr uint32_t BOFF   = (TERMS == 1) ? TILEB : 2 * TILEB;  // B_h tile offset
    constexpr uint32_t STG = NTILES * TILEB;
    extern __shared__ char smem[];
    const uint32_t sb = smem_u32(smem);
    const int tid  = threadIdx.x;
    const int lane = tid & 31, wid = tid >> 5;
    const int wr = wid >> 1, wc = wid & 1;       // 2 x 2 warp grid
    const int mr = wr * 64, ncol = wc * 64;      // warp tile 64 x 64
    const int brow = blockIdx.y * 128, bcol = blockIdx.x * 128, bz = blockIdx.z;

    const __nv_bfloat16* pAh = Ah + (size_t)bz * sA + (size_t)brow * K;
    const __nv_bfloat16* pAl = (TERMS >= 2) ? Al + (size_t)bz * sA + (size_t)brow * K : nullptr;
    const __nv_bfloat16* pBh = Bh + (size_t)bz * sB + (size_t)bcol * K;
    const __nv_bfloat16* pBl = (TERMS == 3) ? Bl + (size_t)bz * sB + (size_t)bcol * K : nullptr;

    auto ld_stage = [&](int chunk, int slot) {
        const uint32_t st = sb + (uint32_t)slot * STG;
        #pragma unroll
        for (int i = 0; i < 4; i++) {
            int idx = tid + i * 128;
            int r = idx >> 2, cc = idx & 3;
            uint32_t sw = swz64((uint32_t)r * 64 + cc * 16);
            size_t g = (size_t)r * K + (size_t)chunk * 32 + cc * 8;
            cpasync16(st + sw, pAh + g);
            if constexpr (TERMS >= 2) cpasync16(st + TILEB + sw, pAl + g);
            cpasync16(st + BOFF + sw, pBh + g);
            if constexpr (TERMS == 3) cpasync16(st + 3 * TILEB + sw, pBl + g);
        }
        cp_commit();
    };

    float acc[4][8][4];
    #pragma unroll
    for (int a = 0; a < 4; a++)
        #pragma unroll
        for (int b = 0; b < 8; b++)
            #pragma unroll
            for (int c = 0; c < 4; c++) acc[a][b][c] = 0.f;

    const int KCH = K >> 5;
    ld_stage(0, 0);
    ld_stage(1, 1);

    const int lm = lane >> 3, lr = lane & 7;
    const uint32_t a_row  = (uint32_t)(mr + ((lm & 1) << 3) + lr);
    const uint32_t a_koff = (uint32_t)((lm >> 1) << 3);
    const uint32_t b_row  = (uint32_t)(ncol + ((lm & 2) ? 8 : 0) + lr);
    const uint32_t b_koff = (uint32_t)((lm & 1) << 3);

    int csl = 0, lsl = 2;   // compute slot, load slot
    for (int c = 0; c < KCH; ++c) {
        cp_wait1();
        __syncthreads();
        if (c + 2 < KCH) {
            ld_stage(c + 2, lsl);
            lsl = (lsl == NST - 1) ? 0 : lsl + 1;
        } else {
            cp_commit();
        }
        const uint32_t st = sb + (uint32_t)csl * STG;
        csl = (csl == NST - 1) ? 0 : csl + 1;
        #pragma unroll
        for (int ks = 0; ks < 2; ++ks) {
            uint32_t aH[4][4], aL[4][4], bH[4][4], bL[4][4];
            #pragma unroll
            for (int mt = 0; mt < 4; ++mt) {
                uint32_t sw = swz64((a_row + mt * 16) * 64 + (ks * 16 + a_koff) * 2);
                ldm4(aH[mt], st + sw);
                if constexpr (TERMS >= 2) ldm4(aL[mt], st + TILEB + sw);
            }
            #pragma unroll
            for (int np = 0; np < 4; ++np) {
                uint32_t sw = swz64((b_row + np * 16) * 64 + (ks * 16 + b_koff) * 2);
                ldm4(bH[np], st + BOFF + sw);
                if constexpr (TERMS == 3) ldm4(bL[np], st + 3 * TILEB + sw);
            }
            #pragma unroll
            for (int mt = 0; mt < 4; ++mt)
                #pragma unroll
                for (int np = 0; np < 4; ++np)
                    #pragma unroll
                    for (int sub = 0; sub < 2; ++sub)
                        mma16816t<FP16>(acc[mt][np * 2 + sub], aH[mt], &bH[np][sub * 2]);
            if constexpr (TERMS == 3) {
                #pragma unroll
                for (int mt = 0; mt < 4; ++mt)
                    #pragma unroll
                    for (int np = 0; np < 4; ++np)
                        #pragma unroll
                        for (int sub = 0; sub < 2; ++sub)
                            mma16816t<FP16>(acc[mt][np * 2 + sub], aH[mt], &bL[np][sub * 2]);
                #pragma unroll
                for (int mt = 0; mt < 4; ++mt)
                    #pragma unroll
                    for (int np = 0; np < 4; ++np)
                        #pragma unroll
                        for (int sub = 0; sub < 2; ++sub)
                            mma16816t<FP16>(acc[mt][np * 2 + sub], aL[mt], &bH[np][sub * 2]);
            }
        }
    }

    // ---------------- epilogue ----------------
    const int rq = lane >> 2;          // 0..7
    const int cq = (lane & 3) * 2;     // 0,2,4,6
    float bv[8][2], b2v[8][2];
    #pragma unroll
    for (int nt = 0; nt < 8; ++nt) {
        int col = bcol + ncol + nt * 8 + cq;
        bv[nt][0] = bias ? bias[col]     : 0.f;
        bv[nt][1] = bias ? bias[col + 1] : 0.f;
        if (EPI == 2) { b2v[nt][0] = b2[col]; b2v[nt][1] = b2[col + 1]; }
    }
    #pragma unroll
    for (int mt = 0; mt < 4; ++mt) {
        #pragma unroll
        for (int half_ = 0; half_ < 2; ++half_) {
            int row = brow + mr + mt * 16 + half_ * 8 + rq;
            float rv = (EPI == 2) ? rs[row] : 0.f;
            #pragma unroll
            for (int nt = 0; nt < 8; ++nt) {
                int col = bcol + ncol + nt * 8 + cq;
                float v0 = acc[mt][nt][half_ * 2 + 0] + bv[nt][0];
                float v1 = acc[mt][nt][half_ * 2 + 1] + bv[nt][1];
                if (EPI == 2) { v0 += rv * b2v[nt][0]; v1 += rv * b2v[nt][1]; }
                size_t idx = (size_t)bz * sC + (size_t)row * N + col;
                if constexpr (EPI == 2) {
                    *(float2*)&Cf[idx] = make_float2(v0, v1);
                } else if constexpr (EPI == 1) {
                    __nv_bfloat16 h0 = __float2bfloat16(v0), h1 = __float2bfloat16(v1);
                    __nv_bfloat16 l0 = __float2bfloat16(v0 - __bfloat162float(h0));
                    __nv_bfloat16 l1 = __float2bfloat16(v1 - __bfloat162float(h1));
                    *(uint32_t*)&Chi[idx] = pack_bf2(h0, h1);
                    *(uint32_t*)&Clo[idx] = pack_bf2(l0, l1);
                } else {  // EPI == 3: fp16 single out
                    __half h0 = __float2half_rn(v0), h1 = __float2half_rn(v1);
                    *(uint32_t*)&((__half*)Chi)[idx] = pack_hf2(h0, h1);
                }
            }
        }
    }
}

// ---------------- fused QK^T + softmax + mask kernel ----------------
// S = q @ k^T (3-term bf16) with the FULL row (N=256) in one CTA, then in-register
// softmax + mask (exp computed ONCE, stored in acc), writing betaF (fp32 d_out),
// beta fp16, and masked rowsum.
// 256 threads = 8 warps, 2x4 grid of 64x64 warp tiles. Block tile 128 x 256. K=512.
#define G4_ATILE (128 * 32 * 2)          // 8 KB
#define G4_BTILE (256 * 32 * 2)          // 16 KB
#define G4_STG   (2 * G4_ATILE + 2 * G4_BTILE)   // 48 KB
#define G4_SMEM  (NST * G4_STG)          // 144 KB

__global__ __launch_bounds__(256, 1)
void qk_softmax_kernel(const __nv_bfloat16* __restrict__ qh, const __nv_bfloat16* __restrict__ ql,
                       const __nv_bfloat16* __restrict__ kh, const __nv_bfloat16* __restrict__ kl,
                       const float* __restrict__ masks,
                       float* __restrict__ betaF, __half* __restrict__ bt16,
                       float* __restrict__ rowsum)
{
    extern __shared__ char smem[];
    __shared__ float red[128][4];
    const uint32_t sb = smem_u32(smem);
    const int tid  = threadIdx.x;
    const int lane = tid & 31, wid = tid >> 5;
    const int wr = wid >> 2, wc = wid & 3;       // 2 x 4 warp grid
    const int mr = wr * 64, ncol = wc * 64;      // warp tile 64 x 64
    const int brow = blockIdx.y * 128, bz = blockIdx.z;

    const __nv_bfloat16* pAh = qh + (size_t)(bz * HW_ + brow) * FQK;
    const __nv_bfloat16* pAl = ql + (size_t)(bz * HW_ + brow) * FQK;
    const __nv_bfloat16* pBh = kh + (size_t)(bz * NTOK) * FQK;
    const __nv_bfloat16* pBl = kl + (size_t)(bz * NTOK) * FQK;

    auto ld_stage = [&](int chunk, int slot) {
        const uint32_t st = sb + (uint32_t)slot * G4_STG;
        #pragma unroll
        for (int i = 0; i < 2; i++) {            // A: 128 rows -> 512 lines / 256 thr
            int idx = tid + i * 256;
            int r = idx >> 2, cc = idx & 3;
            uint32_t sw = swz64((uint32_t)r * 64 + cc * 16);
            size_t g = (size_t)r * FQK + (size_t)chunk * 32 + cc * 8;
            cpasync16(st + sw,            pAh + g);
            cpasync16(st + G4_ATILE + sw, pAl + g);
        }
        #pragma unroll
        for (int i = 0; i < 4; i++) {            // B: 256 rows -> 1024 lines / 256 thr
            int idx = tid + i * 256;
            int r = idx >> 2, cc = idx & 3;
            uint32_t sw = swz64((uint32_t)r * 64 + cc * 16);
            size_t g = (size_t)r * FQK + (size_t)chunk * 32 + cc * 8;
            cpasync16(st + 2 * G4_ATILE + sw,            pBh + g);
            cpasync16(st + 2 * G4_ATILE + G4_BTILE + sw, pBl + g);
        }
        cp_commit();
    };

    float acc[4][8][4];
    #pragma unroll
    for (int a = 0; a < 4; a++)
        #pragma unroll
        for (int b = 0; b < 8; b++)
            #pragma unroll
            for (int c = 0; c < 4; c++) acc[a][b][c] = 0.f;

    const int KCH = FQK >> 5;   // 16
    ld_stage(0, 0);
    ld_stage(1, 1);

    const int lm = lane >> 3, lr = lane & 7;
    const uint32_t a_row  = (uint32_t)(mr + ((lm & 1) << 3) + lr);
    const uint32_t a_koff = (uint32_t)((lm >> 1) << 3);
    const uint32_t b_row  = (uint32_t)(ncol + ((lm & 2) ? 8 : 0) + lr);
    const uint32_t b_koff = (uint32_t)((lm & 1) << 3);

    int csl = 0, lsl = 2;
    for (int c = 0; c < KCH; ++c) {
        cp_wait1();
        __syncthreads();
        if (c + 2 < KCH) {
            ld_stage(c + 2, lsl);
            lsl = (lsl == NST - 1) ? 0 : lsl + 1;
        } else {
            cp_commit();
        }
        const uint32_t st = sb + (uint32_t)csl * G4_STG;
        csl = (csl == NST - 1) ? 0 : csl + 1;
        #pragma unroll
        for (int ks = 0; ks < 2; ++ks) {
            uint32_t aH[4][4], aL[4][4], bH[4][4], bL[4][4];
            #pragma unroll
            for (int mt = 0; mt < 4; ++mt) {
                uint32_t sw = swz64((a_row + mt * 16) * 64 + (ks * 16 + a_koff) * 2);
                ldm4(aH[mt], st + sw);
                ldm4(aL[mt], st + G4_ATILE + sw);
            }
            #pragma unroll
            for (int np = 0; np < 4; ++np) {
                uint32_t sw = swz64((b_row + np * 16) * 64 + (ks * 16 + b_koff) * 2);
                ldm4(bH[np], st + 2 * G4_ATILE + sw);
                ldm4(bL[np], st + 2 * G4_ATILE + G4_BTILE + sw);
            }
            #pragma unroll
            for (int mt = 0; mt < 4; ++mt)
                #pragma unroll
                for (int np = 0; np < 4; ++np)
                    #pragma unroll
                    for (int sub = 0; sub < 2; ++sub)
                        mma16816t<false>(acc[mt][np * 2 + sub], aH[mt], &bH[np][sub * 2]);
            #pragma unroll
            for (int mt = 0; mt < 4; ++mt)
                #pragma unroll
                for (int np = 0; np < 4; ++np)
                    #pragma unroll
                    for (int sub = 0; sub < 2; ++sub)
                        mma16816t<false>(acc[mt][np * 2 + sub], aH[mt], &bL[np][sub * 2]);
            #pragma unroll
            for (int mt = 0; mt < 4; ++mt)
                #pragma unroll
                for (int np = 0; np < 4; ++np)
                    #pragma unroll
                    for (int sub = 0; sub < 2; ++sub)
                        mma16816t<false>(acc[mt][np * 2 + sub], aL[mt], &bH[np][sub * 2]);
        }
    }

    // ---------------- fused softmax epilogue (exp computed once) ----------------
    const int rq = lane >> 2;          // 0..7
    const int cq = (lane & 3) * 2;     // 0,2,4,6
    const bool qlead = ((lane & 3) == 0);

    // 1) row max: per-thread over 16 cols, quad-reduce, cross-warp via smem
    float rmax[8];
    #pragma unroll
    for (int mt = 0; mt < 4; ++mt)
        #pragma unroll
        for (int h = 0; h < 2; ++h) {
            float m = -1e30f;
            #pragma unroll
            for (int nt = 0; nt < 8; ++nt) {
                m = fmaxf(m, acc[mt][nt][h * 2 + 0]);
                m = fmaxf(m, acc[mt][nt][h * 2 + 1]);
            }
            m = fmaxf(m, __shfl_xor_sync(0xffffffffu, m, 1));
            m = fmaxf(m, __shfl_xor_sync(0xffffffffu, m, 2));
            if (qlead) red[mr + mt * 16 + h * 8 + rq][wc] = m;
        }
    __syncthreads();
    #pragma unroll
    for (int mt = 0; mt < 4; ++mt)
        #pragma unroll
        for (int h = 0; h < 2; ++h) {
            int r = mr + mt * 16 + h * 8 + rq;
            rmax[mt * 2 + h] = fmaxf(fmaxf(red[r][0], red[r][1]), fmaxf(red[r][2], red[r][3]));
        }
    __syncthreads();

    // 2) transform acc -> exp(acc - rmax) IN PLACE, then row-sum
    float rden[8];
    #pragma unroll
    for (int mt = 0; mt < 4; ++mt)
        #pragma unroll
        for (int h = 0; h < 2; ++h) {
            float s = 0.f;
            const float mx = rmax[mt * 2 + h];
            #pragma unroll
            for (int nt = 0; nt < 8; ++nt) {
                float e0 = __expf(acc[mt][nt][h * 2 + 0] - mx);
                float e1 = __expf(acc[mt][nt][h * 2 + 1] - mx);
                acc[mt][nt][h * 2 + 0] = e0;
                acc[mt][nt][h * 2 + 1] = e1;
                s += e0 + e1;
            }
            s += __shfl_xor_sync(0xffffffffu, s, 1);
            s += __shfl_xor_sync(0xffffffffu, s, 2);
            if (qlead) red[mr + mt * 16 + h * 8 + rq][wc] = s;
        }
    __syncthreads();
    #pragma unroll
    for (int mt = 0; mt < 4; ++mt)
        #pragma unroll
        for (int h = 0; h < 2; ++h) {
            int r = mr + mt * 16 + h * 8 + rq;
            rden[mt * 2 + h] = 1.f / (red[r][0] + red[r][1] + red[r][2] + red[r][3]);
        }
    __syncthreads();

    // 3) write beta (fp32 + fp16) with mask; accumulate masked rowsum
    #pragma unroll
    for (int mt = 0; mt < 4; ++mt)
        #pragma unroll
        for (int h = 0; h < 2; ++h) {
            const int rloc = mr + mt * 16 + h * 8 + rq;
            const size_t grow = (size_t)(bz * HW_ + brow + rloc);
            const float inv = rden[mt * 2 + h];
            float msum = 0.f;
            #pragma unroll
            for (int nt = 0; nt < 8; ++nt) {
                int col = ncol + nt * 8 + cq;
                float m0 = masks[(bz << 8) + col], m1 = masks[(bz << 8) + col + 1];
                float b0 = acc[mt][nt][h * 2 + 0] * inv * m0;
                float b1 = acc[mt][nt][h * 2 + 1] * inv * m1;
                *(float2*)&betaF[(grow << 8) + col] = make_float2(b0, b1);
                *(uint32_t*)&bt16[(grow << 8) + col] =
                    pack_hf2(__float2half_rn(b0), __float2half_rn(b1));
                msum += b0 + b1;
            }
            msum += __shfl_xor_sync(0xffffffffu, msum, 1);
            msum += __shfl_xor_sync(0xffffffffu, msum, 2);
            if (qlead) red[rloc][wc] = msum;
        }
    __syncthreads();
    if (wc == 0 && qlead) {
        #pragma unroll
        for (int mt = 0; mt < 4; ++mt)
            #pragma unroll
            for (int h = 0; h < 2; ++h) {
                const int rloc = mr + mt * 16 + h * 8 + rq;
                rowsum[(size_t)(bz * HW_ + brow + rloc)] =
                    red[rloc][0] + red[rloc][1] + red[rloc][2] + red[rloc][3];
            }
    }
}

// ---------------- host launch ----------------
#define HS3 (NST * 4 * TILEB)   // 98304
#define HS1 (NST * 2 * TILEB)   // 49152

extern "C" void kernel_launch(void* const* d_in, const int* in_sizes, int n_in,
                              void* d_out, int out_size)
{
    (void)in_sizes; (void)n_in; (void)out_size;
    const float* x1    = (const float*)d_in[0];
    const float* x2    = (const float*)d_in[1];
    const float* masks = (const float*)d_in[2];
    const float* Wq    = (const float*)d_in[3];
    const float* bq    = (const float*)d_in[4];
    const float* Wk    = (const float*)d_in[5];
    const float* bk    = (const float*)d_in[6];
    const float* Wv    = (const float*)d_in[7];
    const float* bv    = (const float*)d_in[8];
    const float* Wo    = (const float*)d_in[9];
    const float* bo    = (const float*)d_in[10];

    float* outp  = (float*)d_out;
    float* betaF = (float*)d_out + O_ELEMS;

    __nv_bfloat16 *x1h,*x1l,*x2h,*x2l,*wqh,*wql,*wkh,*wkl,*wvh,*wvl,*woh,*wol;
    __nv_bfloat16 *qh,*ql,*kh,*kl;
    __half *wvot16,*x2t16,*bt16,*bx16;
    float *rowsum, *bvwo;
    cudaGetSymbolAddress((void**)&x1h, g_x1h); cudaGetSymbolAddress((void**)&x1l, g_x1l);
    cudaGetSymbolAddress((void**)&x2h, g_x2h); cudaGetSymbolAddress((void**)&x2l, g_x2l);
    cudaGetSymbolAddress((void**)&wqh, g_wqh); cudaGetSymbolAddress((void**)&wql, g_wql);
    cudaGetSymbolAddress((void**)&wkh, g_wkh); cudaGetSymbolAddress((void**)&wkl, g_wkl);
    cudaGetSymbolAddress((void**)&wvh, g_wvh); cudaGetSymbolAddress((void**)&wvl, g_wvl);
    cudaGetSymbolAddress((void**)&woh, g_woh); cudaGetSymbolAddress((void**)&wol, g_wol);
    cudaGetSymbolAddress((void**)&qh, g_qh);   cudaGetSymbolAddress((void**)&ql, g_ql);
    cudaGetSymbolAddress((void**)&kh, g_kh);   cudaGetSymbolAddress((void**)&kl, g_kl);
    cudaGetSymbolAddress((void**)&wvot16, g_wvot16);
    cudaGetSymbolAddress((void**)&x2t16, g_x2t16);
    cudaGetSymbolAddress((void**)&bt16, g_bt16);
    cudaGetSymbolAddress((void**)&bx16, g_bx16);
    cudaGetSymbolAddress((void**)&rowsum, g_rowsum);
    cudaGetSymbolAddress((void**)&bvwo, g_bvwo);

    cudaFuncSetAttribute((const void*)hmma_gemm<1,false,3>, cudaFuncAttributeMaxDynamicSharedMemorySize, HS3);
    cudaFuncSetAttribute((const void*)hmma_gemm<3,false,3>, cudaFuncAttributeMaxDynamicSharedMemorySize, HS3);
    cudaFuncSetAttribute((const void*)hmma_gemm<3,true,1>,  cudaFuncAttributeMaxDynamicSharedMemorySize, HS1);
    cudaFuncSetAttribute((const void*)hmma_gemm<2,true,1>,  cudaFuncAttributeMaxDynamicSharedMemorySize, HS1);
    cudaFuncSetAttribute((const void*)qk_softmax_kernel,    cudaFuncAttributeMaxDynamicSharedMemorySize, G4_SMEM);

    // ---- streams/events: created ONCE, kept alive (inside the harness baseline) ----
    static cudaStream_t s2 = nullptr, s3 = nullptr;
    static cudaEvent_t  e_start = nullptr, e_g2 = nullptr, e_gW = nullptr;
    if (s2 == nullptr) {
        cudaStreamCreateWithFlags(&s2, cudaStreamNonBlocking);
        cudaStreamCreateWithFlags(&s3, cudaStreamNonBlocking);
        cudaEventCreateWithFlags(&e_start, cudaEventDisableTiming);
        cudaEventCreateWithFlags(&e_g2,    cudaEventDisableTiming);
        cudaEventCreateWithFlags(&e_gW,    cudaEventDisableTiming);
    }
    cudaStream_t s0 = 0;

    cudaEventRecord(e_start, s0);
    cudaStreamWaitEvent(s2, e_start, 0);
    cudaStreamWaitEvent(s3, e_start, 0);

    // ===== stream s0: x1 -> q chain =====
    {
        int n4 = (M_FLAT * IMG_CH) / 4;
        split_kernel<<<(n4 + 255) / 256, 256, 0, s0>>>(x1, x1h, x1l, n4);
    }
    transpose_split_kernel<<<dim3(FQK/32, IMG_CH/32), dim3(32,8), 0, s0>>>(Wq, wqh, wql, IMG_CH, FQK);
    hmma_gemm<1,false,3><<<dim3(FQK/128, M_FLAT/128, 1), 128, HS3, s0>>>(
        x1h, x1l, wqh, wql, bq, nullptr, qh, ql, nullptr, nullptr,
        FQK, IMG_CH, 0, 0, 0);

    // ===== stream s2: x2 -> k chain + x2^T (fp16 single) =====
    {
        int n4 = (M_FLAT * TEXT_CH) / 4;
        split_kernel<<<(n4 + 255) / 256, 256, 0, s2>>>(x2, x2h, x2l, n4);
    }
    transpose_split_kernel<<<dim3(FQK/32, TEXT_CH/32), dim3(32,8), 0, s2>>>(Wk, wkh, wkl, TEXT_CH, FQK);
    hmma_gemm<1,false,3><<<dim3(FQK/128, M_FLAT/128, 1), 128, HS3, s2>>>(
        x2h, x2l, wkh, wkl, bk, nullptr, kh, kl, nullptr, nullptr,
        FQK, TEXT_CH, 0, 0, 0);
    transpose_f2h_kernel<<<dim3(TEXT_CH/32, NTOK/32, BATCH), dim3(32,8), 0, s2>>>(
        x2, x2t16, NTOK, TEXT_CH);
    cudaEventRecord(e_g2, s2);

    // ===== stream s3: fused weight Wvo^T (bf16 3-term -> fp16 single) + bias precompute =====
    {
        int n4 = (TEXT_CH * IMG_CH) / 4;
        split_kernel<<<(n4 + 255) / 256, 256, 0, s3>>>(Wv, wvh, wvl, n4);   // PLAIN split [768,1024]
    }
    transpose_split_kernel<<<dim3(IMG_CH/32, IMG_CH/32), dim3(32,8), 0, s3>>>(Wo, woh, wol, IMG_CH, IMG_CH);
    bias_vo_kernel<<<IMG_CH/256, 256, 0, s3>>>(bv, Wo, bvwo);
    // Wvo^T[f,c] = sum_k Wo^T[f,k] * Wv[c,k]  (M=1024, N=768, K=1024), fp16 single out
    hmma_gemm<3,false,3><<<dim3(TEXT_CH/128, IMG_CH/128, 1), 128, HS3, s3>>>(
        woh, wol, wvh, wvl, nullptr, nullptr, (__nv_bfloat16*)wvot16, nullptr, nullptr, nullptr,
        TEXT_CH, IMG_CH, 0, 0, 0);
    cudaEventRecord(e_gW, s3);

    // ===== join on s0: attention chain =====
    cudaStreamWaitEvent(s0, e_g2, 0);
    // fused g4 + softmax: S = q@k^T -> softmax*mask -> betaF (d_out) + beta fp16 + rowsum
    qk_softmax_kernel<<<dim3(1, HW_/128, BATCH), 256, G4_SMEM, s0>>>(
        qh, ql, kh, kl, masks, betaF, bt16, rowsum);
    // g5b: bx2 = beta @ x2 (batched; fp16 1-term, occ 3) -> fp16 single
    hmma_gemm<3,true,1><<<dim3(TEXT_CH/128, HW_/128, BATCH), 128, HS1, s0>>>(
        (__nv_bfloat16*)bt16, nullptr, (__nv_bfloat16*)x2t16, nullptr,
        nullptr, nullptr, (__nv_bfloat16*)bx16, nullptr, nullptr, nullptr,
        TEXT_CH, NTOK, (size_t)HW_ * NTOK, (size_t)TEXT_CH * NTOK, (size_t)HW_ * TEXT_CH);
    // g6b: out = bx2 @ Wvo^T + rowsum*bvwo + bo (fp16 1-term, occ 3, M=16384, N=1024, K=768)
    cudaStreamWaitEvent(s0, e_gW, 0);
    hmma_gemm<2,true,1><<<dim3(IMG_CH/128, M_FLAT/128, 1), 128, HS1, s0>>>(
        (__nv_bfloat16*)bx16, nullptr, (__nv_bfloat16*)wvot16, nullptr,
        bo, outp, nullptr, nullptr, rowsum, bvwo,
        IMG_CH, TEXT_CH, 0, 0, 0);
}

// round 15
// speedup vs baseline: 1.0326x; 1.0326x over previous
#include <cuda_runtime.h>
#include <cuda_bf16.h>
#include <cuda_fp16.h>
#include <cstdint>
#include <cstddef>

// ---------------- problem constants ----------------
#define BATCH   64
#define HW_     256
#define NTOK    256
#define IMG_CH  1024
#define TEXT_CH 768
#define FQK     512
#define M_FLAT  (BATCH * HW_)                       // 16384
#define O_ELEMS ((size_t)M_FLAT * IMG_CH)           // 16,777,216

// ---------------- scratch ----------------
#define DECLB(name, n) __device__ __align__(256) __nv_bfloat16 name[(size_t)(n)]
#define DECLH(name, n) __device__ __align__(256) __half name[(size_t)(n)]
DECLB(g_x1h, (size_t)M_FLAT * IMG_CH);  DECLB(g_x1l, (size_t)M_FLAT * IMG_CH);
DECLB(g_x2h, (size_t)M_FLAT * TEXT_CH); DECLB(g_x2l, (size_t)M_FLAT * TEXT_CH);
DECLB(g_wqh, (size_t)FQK * IMG_CH);     DECLB(g_wql, (size_t)FQK * IMG_CH);     // Wq^T [512,1024]
DECLB(g_wkh, (size_t)FQK * TEXT_CH);    DECLB(g_wkl, (size_t)FQK * TEXT_CH);    // Wk^T [512,768]
DECLB(g_wvh, (size_t)TEXT_CH * IMG_CH); DECLB(g_wvl, (size_t)TEXT_CH * IMG_CH); // Wv PLAIN split [768,1024]
DECLB(g_woh, (size_t)IMG_CH * IMG_CH);  DECLB(g_wol, (size_t)IMG_CH * IMG_CH);  // Wo^T [1024,1024]
DECLB(g_qh,  (size_t)M_FLAT * FQK);     DECLB(g_ql,  (size_t)M_FLAT * FQK);
DECLB(g_kh,  (size_t)M_FLAT * FQK);     DECLB(g_kl,  (size_t)M_FLAT * FQK);
// fp16 beta-path scratch (all SINGLE precision fp16)
DECLH(g_wvot16, (size_t)IMG_CH * TEXT_CH);            // (Wv.Wo)^T fp16 [1024,768]
DECLH(g_x2t16,  (size_t)BATCH * TEXT_CH * NTOK);      // x2^T fp16 per batch
DECLH(g_bt16,   (size_t)M_FLAT * NTOK);               // beta fp16
DECLH(g_bx16,   (size_t)M_FLAT * TEXT_CH);            // beta@x2 fp16
__device__ __align__(256) float g_rowsum[M_FLAT];     // masked rowsum of beta
__device__ __align__(256) float g_bvwo[IMG_CH];       // bv @ Wo

// ---------------- PTX helpers (baseline PTX only) ----------------
__device__ __forceinline__ uint32_t smem_u32(const void* p) {
    uint32_t a;
    asm("{ .reg .u64 t; cvta.to.shared.u64 t, %1; cvt.u32.u64 %0, t; }" : "=r"(a) : "l"(p));
    return a;
}
__device__ __forceinline__ void cpasync16(uint32_t dst, const void* src) {
    asm volatile("cp.async.cg.shared.global [%0], [%1], 16;" :: "r"(dst), "l"(src));
}
__device__ __forceinline__ void cp_commit() { asm volatile("cp.async.commit_group;" ::: "memory"); }
__device__ __forceinline__ void cp_wait1()  { asm volatile("cp.async.wait_group 1;" ::: "memory"); }

__device__ __forceinline__ void ldm4(uint32_t* r, uint32_t addr) {
    asm volatile("ldmatrix.sync.aligned.m8n8.x4.shared.b16 {%0,%1,%2,%3}, [%4];"
                 : "=r"(r[0]), "=r"(r[1]), "=r"(r[2]), "=r"(r[3]) : "r"(addr));
}
template<bool FP16>
__device__ __forceinline__ void mma16816t(float* d, const uint32_t* a, const uint32_t* b) {
    if constexpr (FP16)
        asm volatile("mma.sync.aligned.m16n8k16.row.col.f32.f16.f16.f32 "
                     "{%0,%1,%2,%3}, {%4,%5,%6,%7}, {%8,%9}, {%0,%1,%2,%3};"
                     : "+f"(d[0]), "+f"(d[1]), "+f"(d[2]), "+f"(d[3])
                     : "r"(a[0]), "r"(a[1]), "r"(a[2]), "r"(a[3]), "r"(b[0]), "r"(b[1]));
    else
        asm volatile("mma.sync.aligned.m16n8k16.row.col.f32.bf16.bf16.f32 "
                     "{%0,%1,%2,%3}, {%4,%5,%6,%7}, {%8,%9}, {%0,%1,%2,%3};"
                     : "+f"(d[0]), "+f"(d[1]), "+f"(d[2]), "+f"(d[3])
                     : "r"(a[0]), "r"(a[1]), "r"(a[2]), "r"(a[3]), "r"(b[0]), "r"(b[1]));
}
// SW64 swizzle for 64-byte rows (8-row atom), conflict-free for cp.async stores + ldmatrix
__device__ __forceinline__ uint32_t swz64(uint32_t off) { return off ^ ((off >> 3) & 0x30); }
__device__ __forceinline__ uint32_t pack_bf2(__nv_bfloat16 a, __nv_bfloat16 b) {
    return (uint32_t)__bfloat16_as_ushort(a) | ((uint32_t)__bfloat16_as_ushort(b) << 16);
}
__device__ __forceinline__ uint32_t pack_hf2(__half a, __half b) {
    return (uint32_t)__half_as_ushort(a) | ((uint32_t)__half_as_ushort(b) << 16);
}

// ---------------- prep kernels ----------------
__global__ void split_kernel(const float* __restrict__ in,
                             __nv_bfloat16* __restrict__ h,
                             __nv_bfloat16* __restrict__ l, int n4) {
    int i = blockIdx.x * blockDim.x + threadIdx.x;
    if (i >= n4) return;
    float4 v = ((const float4*)in)[i];
    __nv_bfloat16 h0 = __float2bfloat16(v.x), h1 = __float2bfloat16(v.y);
    __nv_bfloat16 h2 = __float2bfloat16(v.z), h3 = __float2bfloat16(v.w);
    __nv_bfloat16 l0 = __float2bfloat16(v.x - __bfloat162float(h0));
    __nv_bfloat16 l1 = __float2bfloat16(v.y - __bfloat162float(h1));
    __nv_bfloat16 l2 = __float2bfloat16(v.z - __bfloat162float(h2));
    __nv_bfloat16 l3 = __float2bfloat16(v.w - __bfloat162float(h3));
    ((uint2*)h)[i] = make_uint2(pack_bf2(h0, h1), pack_bf2(h2, h3));
    ((uint2*)l)[i] = make_uint2(pack_bf2(l0, l1), pack_bf2(l2, l3));
}

// W (R x C row-major) -> WT hi/lo (C x R row-major), bf16
__global__ void transpose_split_kernel(const float* __restrict__ W,
                                       __nv_bfloat16* __restrict__ Th,
                                       __nv_bfloat16* __restrict__ Tl,
                                       int R, int C) {
    __shared__ float t[32][33];
    int c0 = blockIdx.x * 32, r0 = blockIdx.y * 32;
    int x = threadIdx.x, y = threadIdx.y;          // (32, 8)
    #pragma unroll
    for (int i = 0; i < 32; i += 8)
        t[y + i][x] = W[(size_t)(r0 + y + i) * C + c0 + x];
    __syncthreads();
    #pragma unroll
    for (int i = 0; i < 32; i += 8) {
        float v = t[x][y + i];
        __nv_bfloat16 hb = __float2bfloat16(v);
        __nv_bfloat16 lb = __float2bfloat16(v - __bfloat162float(hb));
        size_t idx = (size_t)(c0 + y + i) * R + r0 + x;
        Th[idx] = hb;
        Tl[idx] = lb;
    }
}

// per batch float [R,C] -> fp16 single [C,R]
__global__ void transpose_f2h_kernel(const float* __restrict__ in,
                                     __half* __restrict__ out, int R, int C) {
    __shared__ float t[32][33];
    const int b = blockIdx.z;
    const int c0 = blockIdx.x * 32, r0 = blockIdx.y * 32;
    const int x = threadIdx.x, y = threadIdx.y;    // (32, 8)
    const size_t base = (size_t)b * R * C;
    #pragma unroll
    for (int i = 0; i < 32; i += 8)
        t[y + i][x] = in[base + (size_t)(r0 + y + i) * C + c0 + x];
    __syncthreads();
    #pragma unroll
    for (int i = 0; i < 32; i += 8)
        out[base + (size_t)(c0 + y + i) * R + r0 + x] = __float2half_rn(t[x][y + i]);
}

// bvwo[f] = sum_k bv[k] * Wo[k,f]
__global__ void bias_vo_kernel(const float* __restrict__ bv,
                               const float* __restrict__ Wo,
                               float* __restrict__ bvwo) {
    int f = blockIdx.x * blockDim.x + threadIdx.x;
    if (f >= IMG_CH) return;
    float s = 0.f;
    for (int k = 0; k < IMG_CH; ++k) s += bv[k] * Wo[(size_t)k * IMG_CH + f];
    bvwo[f] = s;
}

// ---------------- HMMA split GEMM (generic) ----------------
// TERMS==3 (bf16): C = AhBh + AhBl + AlBh. Tiles Ah|Al|Bh|Bl.
// TERMS==1 (fp16): C = AB (both single). Tiles A|B.
// A: [M,K] row-major, B: [N,K] row-major. BM=BN=128, BK=32, 3-stage cp.async ring.
// 128 threads (4 warps, 2x2 grid of 64x64 warp tiles), 2 CTAs/SM (occ 3 spills: R14).
// Term-major MMA order. EPI 1: hi/lo bf16 split + bias. EPI 2: fp32 + bias + rs*b2.
// EPI 3: fp16 SINGLE out (Chi as __half*).
#define NST   3
#define TILEB (128 * 32 * 2)            // 8 KB per sub-tile

template<int EPI, bool FP16, int TERMS>
__global__ __launch_bounds__(128, 2)
void hmma_gemm(const __nv_bfloat16* __restrict__ Ah, const __nv_bfloat16* __restrict__ Al,
               const __nv_bfloat16* __restrict__ Bh, const __nv_bfloat16* __restrict__ Bl,
               const float* __restrict__ bias,
               float* __restrict__ Cf,
               __nv_bfloat16* __restrict__ Chi, __nv_bfloat16* __restrict__ Clo,
               const float* __restrict__ rs, const float* __restrict__ b2,
               int N, int K, size_t sA, size_t sB, size_t sC)
{
    constexpr uint32_t NTILES = (TERMS == 3) ? 4 : 2;
    constexpr uint32_t BOFF   = (TERMS == 1) ? TILEB : 2 * TILEB;  // B_h tile offset
    constexpr uint32_t STG = NTILES * TILEB;
    extern __shared__ char smem[];
    const uint32_t sb = smem_u32(smem);
    const int tid  = threadIdx.x;
    const int lane = tid & 31, wid = tid >> 5;
    const int wr = wid >> 1, wc = wid & 1;       // 2 x 2 warp grid
    const int mr = wr * 64, ncol = wc * 64;      // warp tile 64 x 64
    const int brow = blockIdx.y * 128, bcol = blockIdx.x * 128, bz = blockIdx.z;

    const __nv_bfloat16* pAh = Ah + (size_t)bz * sA + (size_t)brow * K;
    const __nv_bfloat16* pAl = (TERMS >= 2) ? Al + (size_t)bz * sA + (size_t)brow * K : nullptr;
    const __nv_bfloat16* pBh = Bh + (size_t)bz * sB + (size_t)bcol * K;
    const __nv_bfloat16* pBl = (TERMS == 3) ? Bl + (size_t)bz * sB + (size_t)bcol * K : nullptr;

    auto ld_stage = [&](int chunk, int slot) {
        const uint32_t st = sb + (uint32_t)slot * STG;
        #pragma unroll
        for (int i = 0; i < 4; i++) {
            int idx = tid + i * 128;
            int r = idx >> 2, cc = idx & 3;
            uint32_t sw = swz64((uint32_t)r * 64 + cc * 16);
            size_t g = (size_t)r * K + (size_t)chunk * 32 + cc * 8;
            cpasync16(st + sw, pAh + g);
            if constexpr (TERMS >= 2) cpasync16(st + TILEB + sw, pAl + g);
            cpasync16(st + BOFF + sw, pBh + g);
            if constexpr (TERMS == 3) cpasync16(st + 3 * TILEB + sw, pBl + g);
        }
        cp_commit();
    };

    float acc[4][8][4];
    #pragma unroll
    for (int a = 0; a < 4; a++)
        #pragma unroll
        for (int b = 0; b < 8; b++)
            #pragma unroll
            for (int c = 0; c < 4; c++) acc[a][b][c] = 0.f;

    const int KCH = K >> 5;
    ld_stage(0, 0);
    ld_stage(1, 1);

    const int lm = lane >> 3, lr = lane & 7;
    const uint32_t a_row  = (uint32_t)(mr + ((lm & 1) << 3) + lr);
    const uint32_t a_koff = (uint32_t)((lm >> 1) << 3);
    const uint32_t b_row  = (uint32_t)(ncol + ((lm & 2) ? 8 : 0) + lr);
    const uint32_t b_koff = (uint32_t)((lm & 1) << 3);

    int csl = 0, lsl = 2;   // compute slot, load slot
    for (int c = 0; c < KCH; ++c) {
        cp_wait1();
        __syncthreads();
        if (c + 2 < KCH) {
            ld_stage(c + 2, lsl);
            lsl = (lsl == NST - 1) ? 0 : lsl + 1;
        } else {
            cp_commit();
        }
        const uint32_t st = sb + (uint32_t)csl * STG;
        csl = (csl == NST - 1) ? 0 : csl + 1;
        #pragma unroll
        for (int ks = 0; ks < 2; ++ks) {
            uint32_t aH[4][4], aL[4][4], bH[4][4], bL[4][4];
            #pragma unroll
            for (int mt = 0; mt < 4; ++mt) {
                uint32_t sw = swz64((a_row + mt * 16) * 64 + (ks * 16 + a_koff) * 2);
                ldm4(aH[mt], st + sw);
                if constexpr (TERMS >= 2) ldm4(aL[mt], st + TILEB + sw);
            }
            #pragma unroll
            for (int np = 0; np < 4; ++np) {
                uint32_t sw = swz64((b_row + np * 16) * 64 + (ks * 16 + b_koff) * 2);
                ldm4(bH[np], st + BOFF + sw);
                if constexpr (TERMS == 3) ldm4(bL[np], st + 3 * TILEB + sw);
            }
            #pragma unroll
            for (int mt = 0; mt < 4; ++mt)
                #pragma unroll
                for (int np = 0; np < 4; ++np)
                    #pragma unroll
                    for (int sub = 0; sub < 2; ++sub)
                        mma16816t<FP16>(acc[mt][np * 2 + sub], aH[mt], &bH[np][sub * 2]);
            if constexpr (TERMS == 3) {
                #pragma unroll
                for (int mt = 0; mt < 4; ++mt)
                    #pragma unroll
                    for (int np = 0; np < 4; ++np)
                        #pragma unroll
                        for (int sub = 0; sub < 2; ++sub)
                            mma16816t<FP16>(acc[mt][np * 2 + sub], aH[mt], &bL[np][sub * 2]);
                #pragma unroll
                for (int mt = 0; mt < 4; ++mt)
                    #pragma unroll
                    for (int np = 0; np < 4; ++np)
                        #pragma unroll
                        for (int sub = 0; sub < 2; ++sub)
                            mma16816t<FP16>(acc[mt][np * 2 + sub], aL[mt], &bH[np][sub * 2]);
            }
        }
    }

    // ---------------- epilogue ----------------
    const int rq = lane >> 2;          // 0..7
    const int cq = (lane & 3) * 2;     // 0,2,4,6
    float bv[8][2], b2v[8][2];
    #pragma unroll
    for (int nt = 0; nt < 8; ++nt) {
        int col = bcol + ncol + nt * 8 + cq;
        bv[nt][0] = bias ? bias[col]     : 0.f;
        bv[nt][1] = bias ? bias[col + 1] : 0.f;
        if (EPI == 2) { b2v[nt][0] = b2[col]; b2v[nt][1] = b2[col + 1]; }
    }
    #pragma unroll
    for (int mt = 0; mt < 4; ++mt) {
        #pragma unroll
        for (int half_ = 0; half_ < 2; ++half_) {
            int row = brow + mr + mt * 16 + half_ * 8 + rq;
            float rv = (EPI == 2) ? rs[row] : 0.f;
            #pragma unroll
            for (int nt = 0; nt < 8; ++nt) {
                int col = bcol + ncol + nt * 8 + cq;
                float v0 = acc[mt][nt][half_ * 2 + 0] + bv[nt][0];
                float v1 = acc[mt][nt][half_ * 2 + 1] + bv[nt][1];
                if (EPI == 2) { v0 += rv * b2v[nt][0]; v1 += rv * b2v[nt][1]; }
                size_t idx = (size_t)bz * sC + (size_t)row * N + col;
                if constexpr (EPI == 2) {
                    *(float2*)&Cf[idx] = make_float2(v0, v1);
                } else if constexpr (EPI == 1) {
                    __nv_bfloat16 h0 = __float2bfloat16(v0), h1 = __float2bfloat16(v1);
                    __nv_bfloat16 l0 = __float2bfloat16(v0 - __bfloat162float(h0));
                    __nv_bfloat16 l1 = __float2bfloat16(v1 - __bfloat162float(h1));
                    *(uint32_t*)&Chi[idx] = pack_bf2(h0, h1);
                    *(uint32_t*)&Clo[idx] = pack_bf2(l0, l1);
                } else {  // EPI == 3: fp16 single out
                    __half h0 = __float2half_rn(v0), h1 = __float2half_rn(v1);
                    *(uint32_t*)&((__half*)Chi)[idx] = pack_hf2(h0, h1);
                }
            }
        }
    }
}

// ---------------- fused QK^T + softmax + mask kernel ----------------
// S = q @ k^T (3-term bf16) with the FULL row (N=256) in one CTA, then in-register
// softmax + mask (exp computed ONCE, stored in acc), writing betaF (fp32 d_out),
// beta fp16, and masked rowsum.
// 256 threads = 8 warps, 2x4 grid of 64x64 warp tiles. Block tile 128 x 256. K=512.
#define G4_ATILE (128 * 32 * 2)          // 8 KB
#define G4_BTILE (256 * 32 * 2)          // 16 KB
#define G4_STG   (2 * G4_ATILE + 2 * G4_BTILE)   // 48 KB
#define G4_SMEM  (NST * G4_STG)          // 144 KB

__global__ __launch_bounds__(256, 1)
void qk_softmax_kernel(const __nv_bfloat16* __restrict__ qh, const __nv_bfloat16* __restrict__ ql,
                       const __nv_bfloat16* __restrict__ kh, const __nv_bfloat16* __restrict__ kl,
                       const float* __restrict__ masks,
                       float* __restrict__ betaF, __half* __restrict__ bt16,
                       float* __restrict__ rowsum)
{
    extern __shared__ char smem[];
    __shared__ float red[128][4];
    const uint32_t sb = smem_u32(smem);
    const int tid  = threadIdx.x;
    const int lane = tid & 31, wid = tid >> 5;
    const int wr = wid >> 2, wc = wid & 3;       // 2 x 4 warp grid
    const int mr = wr * 64, ncol = wc * 64;      // warp tile 64 x 64
    const int brow = blockIdx.y * 128, bz = blockIdx.z;

    const __nv_bfloat16* pAh = qh + (size_t)(bz * HW_ + brow) * FQK;
    const __nv_bfloat16* pAl = ql + (size_t)(bz * HW_ + brow) * FQK;
    const __nv_bfloat16* pBh = kh + (size_t)(bz * NTOK) * FQK;
    const __nv_bfloat16* pBl = kl + (size_t)(bz * NTOK) * FQK;

    auto ld_stage = [&](int chunk, int slot) {
        const uint32_t st = sb + (uint32_t)slot * G4_STG;
        #pragma unroll
        for (int i = 0; i < 2; i++) {            // A: 128 rows -> 512 lines / 256 thr
            int idx = tid + i * 256;
            int r = idx >> 2, cc = idx & 3;
            uint32_t sw = swz64((uint32_t)r * 64 + cc * 16);
            size_t g = (size_t)r * FQK + (size_t)chunk * 32 + cc * 8;
            cpasync16(st + sw,            pAh + g);
            cpasync16(st + G4_ATILE + sw, pAl + g);
        }
        #pragma unroll
        for (int i = 0; i < 4; i++) {            // B: 256 rows -> 1024 lines / 256 thr
            int idx = tid + i * 256;
            int r = idx >> 2, cc = idx & 3;
            uint32_t sw = swz64((uint32_t)r * 64 + cc * 16);
            size_t g = (size_t)r * FQK + (size_t)chunk * 32 + cc * 8;
            cpasync16(st + 2 * G4_ATILE + sw,            pBh + g);
            cpasync16(st + 2 * G4_ATILE + G4_BTILE + sw, pBl + g);
        }
        cp_commit();
    };

    float acc[4][8][4];
    #pragma unroll
    for (int a = 0; a < 4; a++)
        #pragma unroll
        for (int b = 0; b < 8; b++)
            #pragma unroll
            for (int c = 0; c < 4; c++) acc[a][b][c] = 0.f;

    const int KCH = FQK >> 5;   // 16
    ld_stage(0, 0);
    ld_stage(1, 1);

    const int lm = lane >> 3, lr = lane & 7;
    const uint32_t a_row  = (uint32_t)(mr + ((lm & 1) << 3) + lr);
    const uint32_t a_koff = (uint32_t)((lm >> 1) << 3);
    const uint32_t b_row  = (uint32_t)(ncol + ((lm & 2) ? 8 : 0) + lr);
    const uint32_t b_koff = (uint32_t)((lm & 1) << 3);

    int csl = 0, lsl = 2;
    for (int c = 0; c < KCH; ++c) {
        cp_wait1();
        __syncthreads();
        if (c + 2 < KCH) {
            ld_stage(c + 2, lsl);
            lsl = (lsl == NST - 1) ? 0 : lsl + 1;
        } else {
            cp_commit();
        }
        const uint32_t st = sb + (uint32_t)csl * G4_STG;
        csl = (csl == NST - 1) ? 0 : csl + 1;
        #pragma unroll
        for (int ks = 0; ks < 2; ++ks) {
            uint32_t aH[4][4], aL[4][4], bH[4][4], bL[4][4];
            #pragma unroll
            for (int mt = 0; mt < 4; ++mt) {
                uint32_t sw = swz64((a_row + mt * 16) * 64 + (ks * 16 + a_koff) * 2);
                ldm4(aH[mt], st + sw);
                ldm4(aL[mt], st + G4_ATILE + sw);
            }
            #pragma unroll
            for (int np = 0; np < 4; ++np) {
                uint32_t sw = swz64((b_row + np * 16) * 64 + (ks * 16 + b_koff) * 2);
                ldm4(bH[np], st + 2 * G4_ATILE + sw);
                ldm4(bL[np], st + 2 * G4_ATILE + G4_BTILE + sw);
            }
            #pragma unroll
            for (int mt = 0; mt < 4; ++mt)
                #pragma unroll
                for (int np = 0; np < 4; ++np)
                    #pragma unroll
                    for (int sub = 0; sub < 2; ++sub)
                        mma16816t<false>(acc[mt][np * 2 + sub], aH[mt], &bH[np][sub * 2]);
            #pragma unroll
            for (int mt = 0; mt < 4; ++mt)
                #pragma unroll
                for (int np = 0; np < 4; ++np)
                    #pragma unroll
                    for (int sub = 0; sub < 2; ++sub)
                        mma16816t<false>(acc[mt][np * 2 + sub], aH[mt], &bL[np][sub * 2]);
            #pragma unroll
            for (int mt = 0; mt < 4; ++mt)
                #pragma unroll
                for (int np = 0; np < 4; ++np)
                    #pragma unroll
                    for (int sub = 0; sub < 2; ++sub)
                        mma16816t<false>(acc[mt][np * 2 + sub], aL[mt], &bH[np][sub * 2]);
        }
    }

    // ---------------- fused softmax epilogue (exp computed once) ----------------
    const int rq = lane >> 2;          // 0..7
    const int cq = (lane & 3) * 2;     // 0,2,4,6
    const bool qlead = ((lane & 3) == 0);

    // 1) row max: per-thread over 16 cols, quad-reduce, cross-warp via smem
    float rmax[8];
    #pragma unroll
    for (int mt = 0; mt < 4; ++mt)
        #pragma unroll
        for (int h = 0; h < 2; ++h) {
            float m = -1e30f;
            #pragma unroll
            for (int nt = 0; nt < 8; ++nt) {
                m = fmaxf(m, acc[mt][nt][h * 2 + 0]);
                m = fmaxf(m, acc[mt][nt][h * 2 + 1]);
            }
            m = fmaxf(m, __shfl_xor_sync(0xffffffffu, m, 1));
            m = fmaxf(m, __shfl_xor_sync(0xffffffffu, m, 2));
            if (qlead) red[mr + mt * 16 + h * 8 + rq][wc] = m;
        }
    __syncthreads();
    #pragma unroll
    for (int mt = 0; mt < 4; ++mt)
        #pragma unroll
        for (int h = 0; h < 2; ++h) {
            int r = mr + mt * 16 + h * 8 + rq;
            rmax[mt * 2 + h] = fmaxf(fmaxf(red[r][0], red[r][1]), fmaxf(red[r][2], red[r][3]));
        }
    __syncthreads();

    // 2) transform acc -> exp(acc - rmax) IN PLACE, then row-sum
    float rden[8];
    #pragma unroll
    for (int mt = 0; mt < 4; ++mt)
        #pragma unroll
        for (int h = 0; h < 2; ++h) {
            float s = 0.f;
            const float mx = rmax[mt * 2 + h];
            #pragma unroll
            for (int nt = 0; nt < 8; ++nt) {
                float e0 = __expf(acc[mt][nt][h * 2 + 0] - mx);
                float e1 = __expf(acc[mt][nt][h * 2 + 1] - mx);
                acc[mt][nt][h * 2 + 0] = e0;
                acc[mt][nt][h * 2 + 1] = e1;
                s += e0 + e1;
            }
            s += __shfl_xor_sync(0xffffffffu, s, 1);
            s += __shfl_xor_sync(0xffffffffu, s, 2);
            if (qlead) red[mr + mt * 16 + h * 8 + rq][wc] = s;
        }
    __syncthreads();
    #pragma unroll
    for (int mt = 0; mt < 4; ++mt)
        #pragma unroll
        for (int h = 0; h < 2; ++h) {
            int r = mr + mt * 16 + h * 8 + rq;
            rden[mt * 2 + h] = 1.f / (red[r][0] + red[r][1] + red[r][2] + red[r][3]);
        }
    __syncthreads();

    // 3) write beta (fp32 + fp16) with mask; accumulate masked rowsum
    #pragma unroll
    for (int mt = 0; mt < 4; ++mt)
        #pragma unroll
        for (int h = 0; h < 2; ++h) {
            const int rloc = mr + mt * 16 + h * 8 + rq;
            const size_t grow = (size_t)(bz * HW_ + brow + rloc);
            const float inv = rden[mt * 2 + h];
            float msum = 0.f;
            #pragma unroll
            for (int nt = 0; nt < 8; ++nt) {
                int col = ncol + nt * 8 + cq;
                float m0 = masks[(bz << 8) + col], m1 = masks[(bz << 8) + col + 1];
                float b0 = acc[mt][nt][h * 2 + 0] * inv * m0;
                float b1 = acc[mt][nt][h * 2 + 1] * inv * m1;
                *(float2*)&betaF[(grow << 8) + col] = make_float2(b0, b1);
                *(uint32_t*)&bt16[(grow << 8) + col] =
                    pack_hf2(__float2half_rn(b0), __float2half_rn(b1));
                msum += b0 + b1;
            }
            msum += __shfl_xor_sync(0xffffffffu, msum, 1);
            msum += __shfl_xor_sync(0xffffffffu, msum, 2);
            if (qlead) red[rloc][wc] = msum;
        }
    __syncthreads();
    if (wc == 0 && qlead) {
        #pragma unroll
        for (int mt = 0; mt < 4; ++mt)
            #pragma unroll
            for (int h = 0; h < 2; ++h) {
                const int rloc = mr + mt * 16 + h * 8 + rq;
                rowsum[(size_t)(bz * HW_ + brow + rloc)] =
                    red[rloc][0] + red[rloc][1] + red[rloc][2] + red[rloc][3];
            }
    }
}

// ---------------- host launch ----------------
#define HS3 (NST * 4 * TILEB)   // 98304
#define HS1 (NST * 2 * TILEB)   // 49152

extern "C" void kernel_launch(void* const* d_in, const int* in_sizes, int n_in,
                              void* d_out, int out_size)
{
    (void)in_sizes; (void)n_in; (void)out_size;
    const float* x1    = (const float*)d_in[0];
    const float* x2    = (const float*)d_in[1];
    const float* masks = (const float*)d_in[2];
    const float* Wq    = (const float*)d_in[3];
    const float* bq    = (const float*)d_in[4];
    const float* Wk    = (const float*)d_in[5];
    const float* bk    = (const float*)d_in[6];
    const float* Wv    = (const float*)d_in[7];
    const float* bv    = (const float*)d_in[8];
    const float* Wo    = (const float*)d_in[9];
    const float* bo    = (const float*)d_in[10];

    float* outp  = (float*)d_out;
    float* betaF = (float*)d_out + O_ELEMS;

    __nv_bfloat16 *x1h,*x1l,*x2h,*x2l,*wqh,*wql,*wkh,*wkl,*wvh,*wvl,*woh,*wol;
    __nv_bfloat16 *qh,*ql,*kh,*kl;
    __half *wvot16,*x2t16,*bt16,*bx16;
    float *rowsum, *bvwo;
    cudaGetSymbolAddress((void**)&x1h, g_x1h); cudaGetSymbolAddress((void**)&x1l, g_x1l);
    cudaGetSymbolAddress((void**)&x2h, g_x2h); cudaGetSymbolAddress((void**)&x2l, g_x2l);
    cudaGetSymbolAddress((void**)&wqh, g_wqh); cudaGetSymbolAddress((void**)&wql, g_wql);
    cudaGetSymbolAddress((void**)&wkh, g_wkh); cudaGetSymbolAddress((void**)&wkl, g_wkl);
    cudaGetSymbolAddress((void**)&wvh, g_wvh); cudaGetSymbolAddress((void**)&wvl, g_wvl);
    cudaGetSymbolAddress((void**)&woh, g_woh); cudaGetSymbolAddress((void**)&wol, g_wol);
    cudaGetSymbolAddress((void**)&qh, g_qh);   cudaGetSymbolAddress((void**)&ql, g_ql);
    cudaGetSymbolAddress((void**)&kh, g_kh);   cudaGetSymbolAddress((void**)&kl, g_kl);
    cudaGetSymbolAddress((void**)&wvot16, g_wvot16);
    cudaGetSymbolAddress((void**)&x2t16, g_x2t16);
    cudaGetSymbolAddress((void**)&bt16, g_bt16);
    cudaGetSymbolAddress((void**)&bx16, g_bx16);
    cudaGetSymbolAddress((void**)&rowsum, g_rowsum);
    cudaGetSymbolAddress((void**)&bvwo, g_bvwo);

    cudaFuncSetAttribute((const void*)hmma_gemm<1,false,3>, cudaFuncAttributeMaxDynamicSharedMemorySize, HS3);
    cudaFuncSetAttribute((const void*)hmma_gemm<3,false,3>, cudaFuncAttributeMaxDynamicSharedMemorySize, HS3);
    cudaFuncSetAttribute((const void*)hmma_gemm<3,true,1>,  cudaFuncAttributeMaxDynamicSharedMemorySize, HS1);
    cudaFuncSetAttribute((const void*)hmma_gemm<2,true,1>,  cudaFuncAttributeMaxDynamicSharedMemorySize, HS1);
    cudaFuncSetAttribute((const void*)qk_softmax_kernel,    cudaFuncAttributeMaxDynamicSharedMemorySize, G4_SMEM);

    // ---- streams/events: created ONCE, kept alive (inside the harness baseline) ----
    static cudaStream_t s2 = nullptr, s3 = nullptr;
    static cudaEvent_t  e_start = nullptr, e_g2 = nullptr, e_gW = nullptr;
    if (s2 == nullptr) {
        cudaStreamCreateWithFlags(&s2, cudaStreamNonBlocking);
        cudaStreamCreateWithFlags(&s3, cudaStreamNonBlocking);
        cudaEventCreateWithFlags(&e_start, cudaEventDisableTiming);
        cudaEventCreateWithFlags(&e_g2,    cudaEventDisableTiming);
        cudaEventCreateWithFlags(&e_gW,    cudaEventDisableTiming);
    }
    cudaStream_t s0 = 0;

    cudaEventRecord(e_start, s0);
    cudaStreamWaitEvent(s2, e_start, 0);
    cudaStreamWaitEvent(s3, e_start, 0);

    // ===== stream s0: x1 -> q chain =====
    {
        int n4 = (M_FLAT * IMG_CH) / 4;
        split_kernel<<<(n4 + 255) / 256, 256, 0, s0>>>(x1, x1h, x1l, n4);
    }
    transpose_split_kernel<<<dim3(FQK/32, IMG_CH/32), dim3(32,8), 0, s0>>>(Wq, wqh, wql, IMG_CH, FQK);
    hmma_gemm<1,false,3><<<dim3(FQK/128, M_FLAT/128, 1), 128, HS3, s0>>>(
        x1h, x1l, wqh, wql, bq, nullptr, qh, ql, nullptr, nullptr,
        FQK, IMG_CH, 0, 0, 0);

    // ===== stream s2: x2 -> k chain + x2^T (fp16 single) =====
    {
        int n4 = (M_FLAT * TEXT_CH) / 4;
        split_kernel<<<(n4 + 255) / 256, 256, 0, s2>>>(x2, x2h, x2l, n4);
    }
    transpose_split_kernel<<<dim3(FQK/32, TEXT_CH/32), dim3(32,8), 0, s2>>>(Wk, wkh, wkl, TEXT_CH, FQK);
    hmma_gemm<1,false,3><<<dim3(FQK/128, M_FLAT/128, 1), 128, HS3, s2>>>(
        x2h, x2l, wkh, wkl, bk, nullptr, kh, kl, nullptr, nullptr,
        FQK, TEXT_CH, 0, 0, 0);
    transpose_f2h_kernel<<<dim3(TEXT_CH/32, NTOK/32, BATCH), dim3(32,8), 0, s2>>>(
        x2, x2t16, NTOK, TEXT_CH);
    cudaEventRecord(e_g2, s2);

    // ===== stream s3: fused weight Wvo^T (bf16 3-term -> fp16 single) + bias precompute =====
    {
        int n4 = (TEXT_CH * IMG_CH) / 4;
        split_kernel<<<(n4 + 255) / 256, 256, 0, s3>>>(Wv, wvh, wvl, n4);   // PLAIN split [768,1024]
    }
    transpose_split_kernel<<<dim3(IMG_CH/32, IMG_CH/32), dim3(32,8), 0, s3>>>(Wo, woh, wol, IMG_CH, IMG_CH);
    bias_vo_kernel<<<IMG_CH/256, 256, 0, s3>>>(bv, Wo, bvwo);
    // Wvo^T[f,c] = sum_k Wo^T[f,k] * Wv[c,k]  (M=1024, N=768, K=1024), fp16 single out
    hmma_gemm<3,false,3><<<dim3(TEXT_CH/128, IMG_CH/128, 1), 128, HS3, s3>>>(
        woh, wol, wvh, wvl, nullptr, nullptr, (__nv_bfloat16*)wvot16, nullptr, nullptr, nullptr,
        TEXT_CH, IMG_CH, 0, 0, 0);
    cudaEventRecord(e_gW, s3);

    // ===== join on s0: attention chain =====
    cudaStreamWaitEvent(s0, e_g2, 0);
    // fused g4 + softmax: S = q@k^T -> softmax*mask -> betaF (d_out) + beta fp16 + rowsum
    qk_softmax_kernel<<<dim3(1, HW_/128, BATCH), 256, G4_SMEM, s0>>>(
        qh, ql, kh, kl, masks, betaF, bt16, rowsum);
    // g5b: bx2 = beta @ x2 (batched; fp16 1-term) -> fp16 single
    hmma_gemm<3,true,1><<<dim3(TEXT_CH/128, HW_/128, BATCH), 128, HS1, s0>>>(
        (__nv_bfloat16*)bt16, nullptr, (__nv_bfloat16*)x2t16, nullptr,
        nullptr, nullptr, (__nv_bfloat16*)bx16, nullptr, nullptr, nullptr,
        TEXT_CH, NTOK, (size_t)HW_ * NTOK, (size_t)TEXT_CH * NTOK, (size_t)HW_ * TEXT_CH);
    // g6b: out = bx2 @ Wvo^T + rowsum*bvwo + bo (fp16 1-term, M=16384, N=1024, K=768)
    cudaStreamWaitEvent(s0, e_gW, 0);
    hmma_gemm<2,true,1><<<dim3(IMG_CH/128, M_FLAT/128, 1), 128, HS1, s0>>>(
        (__nv_bfloat16*)bx16, nullptr, (__nv_bfloat16*)wvot16, nullptr,
        bo, outp, nullptr, nullptr, rowsum, bvwo,
        IMG_CH, TEXT_CH, 0, 0, 0);
}

// round 16
// speedup vs baseline: 1.0378x; 1.0050x over previous
#include <cuda_runtime.h>
#include <cuda_bf16.h>
#include <cuda_fp16.h>
#include <cstdint>
#include <cstddef>

// ---------------- problem constants ----------------
#define BATCH   64
#define HW_     256
#define NTOK    256
#define IMG_CH  1024
#define TEXT_CH 768
#define FQK     512
#define M_FLAT  (BATCH * HW_)                       // 16384
#define O_ELEMS ((size_t)M_FLAT * IMG_CH)           // 16,777,216

// ---------------- scratch ----------------
#define DECLB(name, n) __device__ __align__(256) __nv_bfloat16 name[(size_t)(n)]
#define DECLH(name, n) __device__ __align__(256) __half name[(size_t)(n)]
DECLB(g_x1h, (size_t)M_FLAT * IMG_CH);  DECLB(g_x1l, (size_t)M_FLAT * IMG_CH);
DECLB(g_x2h, (size_t)M_FLAT * TEXT_CH); DECLB(g_x2l, (size_t)M_FLAT * TEXT_CH);
DECLB(g_wqh, (size_t)FQK * IMG_CH);     DECLB(g_wql, (size_t)FQK * IMG_CH);     // Wq^T [512,1024]
DECLB(g_wkh, (size_t)FQK * TEXT_CH);    DECLB(g_wkl, (size_t)FQK * TEXT_CH);    // Wk^T [512,768]
DECLB(g_wvh, (size_t)TEXT_CH * IMG_CH); DECLB(g_wvl, (size_t)TEXT_CH * IMG_CH); // Wv PLAIN split [768,1024]
DECLB(g_woh, (size_t)IMG_CH * IMG_CH);  DECLB(g_wol, (size_t)IMG_CH * IMG_CH);  // Wo^T [1024,1024]
DECLB(g_qh,  (size_t)M_FLAT * FQK);     DECLB(g_ql,  (size_t)M_FLAT * FQK);
DECLB(g_kh,  (size_t)M_FLAT * FQK);     DECLB(g_kl,  (size_t)M_FLAT * FQK);
// fp16 beta-path scratch (all SINGLE precision fp16)
DECLH(g_wvot16, (size_t)IMG_CH * TEXT_CH);            // (Wv.Wo)^T fp16 [1024,768]
DECLH(g_x2t16,  (size_t)BATCH * TEXT_CH * NTOK);      // x2^T fp16 per batch
DECLH(g_bt16,   (size_t)M_FLAT * NTOK);               // beta fp16
DECLH(g_bx16,   (size_t)M_FLAT * TEXT_CH);            // beta@x2 fp16
__device__ __align__(256) float g_rowsum[M_FLAT];     // masked rowsum of beta
__device__ __align__(256) float g_bvwo[IMG_CH];       // bv @ Wo

// ---------------- PTX helpers (baseline PTX only) ----------------
__device__ __forceinline__ uint32_t smem_u32(const void* p) {
    uint32_t a;
    asm("{ .reg .u64 t; cvta.to.shared.u64 t, %1; cvt.u32.u64 %0, t; }" : "=r"(a) : "l"(p));
    return a;
}
__device__ __forceinline__ void cpasync16(uint32_t dst, const void* src) {
    asm volatile("cp.async.cg.shared.global [%0], [%1], 16;" :: "r"(dst), "l"(src));
}
__device__ __forceinline__ void cp_commit() { asm volatile("cp.async.commit_group;" ::: "memory"); }
__device__ __forceinline__ void cp_wait1()  { asm volatile("cp.async.wait_group 1;" ::: "memory"); }

__device__ __forceinline__ void ldm4(uint32_t* r, uint32_t addr) {
    asm volatile("ldmatrix.sync.aligned.m8n8.x4.shared.b16 {%0,%1,%2,%3}, [%4];"
                 : "=r"(r[0]), "=r"(r[1]), "=r"(r[2]), "=r"(r[3]) : "r"(addr));
}
template<bool FP16>
__device__ __forceinline__ void mma16816t(float* d, const uint32_t* a, const uint32_t* b) {
    if constexpr (FP16)
        asm volatile("mma.sync.aligned.m16n8k16.row.col.f32.f16.f16.f32 "
                     "{%0,%1,%2,%3}, {%4,%5,%6,%7}, {%8,%9}, {%0,%1,%2,%3};"
                     : "+f"(d[0]), "+f"(d[1]), "+f"(d[2]), "+f"(d[3])
                     : "r"(a[0]), "r"(a[1]), "r"(a[2]), "r"(a[3]), "r"(b[0]), "r"(b[1]));
    else
        asm volatile("mma.sync.aligned.m16n8k16.row.col.f32.bf16.bf16.f32 "
                     "{%0,%1,%2,%3}, {%4,%5,%6,%7}, {%8,%9}, {%0,%1,%2,%3};"
                     : "+f"(d[0]), "+f"(d[1]), "+f"(d[2]), "+f"(d[3])
                     : "r"(a[0]), "r"(a[1]), "r"(a[2]), "r"(a[3]), "r"(b[0]), "r"(b[1]));
}
// SW64 swizzle for 64-byte rows (8-row atom), conflict-free for cp.async stores + ldmatrix
__device__ __forceinline__ uint32_t swz64(uint32_t off) { return off ^ ((off >> 3) & 0x30); }
__device__ __forceinline__ uint32_t pack_bf2(__nv_bfloat16 a, __nv_bfloat16 b) {
    return (uint32_t)__bfloat16_as_ushort(a) | ((uint32_t)__bfloat16_as_ushort(b) << 16);
}
__device__ __forceinline__ uint32_t pack_hf2(__half a, __half b) {
    return (uint32_t)__half_as_ushort(a) | ((uint32_t)__half_as_ushort(b) << 16);
}

// ---------------- prep kernels ----------------
__global__ void split_kernel(const float* __restrict__ in,
                             __nv_bfloat16* __restrict__ h,
                             __nv_bfloat16* __restrict__ l, int n4) {
    int i = blockIdx.x * blockDim.x + threadIdx.x;
    if (i >= n4) return;
    float4 v = ((const float4*)in)[i];
    __nv_bfloat16 h0 = __float2bfloat16(v.x), h1 = __float2bfloat16(v.y);
    __nv_bfloat16 h2 = __float2bfloat16(v.z), h3 = __float2bfloat16(v.w);
    __nv_bfloat16 l0 = __float2bfloat16(v.x - __bfloat162float(h0));
    __nv_bfloat16 l1 = __float2bfloat16(v.y - __bfloat162float(h1));
    __nv_bfloat16 l2 = __float2bfloat16(v.z - __bfloat162float(h2));
    __nv_bfloat16 l3 = __float2bfloat16(v.w - __bfloat162float(h3));
    ((uint2*)h)[i] = make_uint2(pack_bf2(h0, h1), pack_bf2(h2, h3));
    ((uint2*)l)[i] = make_uint2(pack_bf2(l0, l1), pack_bf2(l2, l3));
}

// W (R x C row-major) -> WT hi/lo (C x R row-major), bf16
__global__ void transpose_split_kernel(const float* __restrict__ W,
                                       __nv_bfloat16* __restrict__ Th,
                                       __nv_bfloat16* __restrict__ Tl,
                                       int R, int C) {
    __shared__ float t[32][33];
    int c0 = blockIdx.x * 32, r0 = blockIdx.y * 32;
    int x = threadIdx.x, y = threadIdx.y;          // (32, 8)
    #pragma unroll
    for (int i = 0; i < 32; i += 8)
        t[y + i][x] = W[(size_t)(r0 + y + i) * C + c0 + x];
    __syncthreads();
    #pragma unroll
    for (int i = 0; i < 32; i += 8) {
        float v = t[x][y + i];
        __nv_bfloat16 hb = __float2bfloat16(v);
        __nv_bfloat16 lb = __float2bfloat16(v - __bfloat162float(hb));
        size_t idx = (size_t)(c0 + y + i) * R + r0 + x;
        Th[idx] = hb;
        Tl[idx] = lb;
    }
}

// per batch float [R,C] -> fp16 single [C,R]
__global__ void transpose_f2h_kernel(const float* __restrict__ in,
                                     __half* __restrict__ out, int R, int C) {
    __shared__ float t[32][33];
    const int b = blockIdx.z;
    const int c0 = blockIdx.x * 32, r0 = blockIdx.y * 32;
    const int x = threadIdx.x, y = threadIdx.y;    // (32, 8)
    const size_t base = (size_t)b * R * C;
    #pragma unroll
    for (int i = 0; i < 32; i += 8)
        t[y + i][x] = in[base + (size_t)(r0 + y + i) * C + c0 + x];
    __syncthreads();
    #pragma unroll
    for (int i = 0; i < 32; i += 8)
        out[base + (size_t)(c0 + y + i) * R + r0 + x] = __float2half_rn(t[x][y + i]);
}

// bvwo[f] = sum_k bv[k] * Wo[k,f]
__global__ void bias_vo_kernel(const float* __restrict__ bv,
                               const float* __restrict__ Wo,
                               float* __restrict__ bvwo) {
    int f = blockIdx.x * blockDim.x + threadIdx.x;
    if (f >= IMG_CH) return;
    float s = 0.f;
    for (int k = 0; k < IMG_CH; ++k) s += bv[k] * Wo[(size_t)k * IMG_CH + f];
    bvwo[f] = s;
}

// ---------------- HMMA split GEMM (generic) ----------------
// TERMS==3 (bf16): C = AhBh + AhBl + AlBh. Tiles Ah|Al|Bh|Bl.
// TERMS==1 (fp16): C = AB (both single). Tiles A|B.
// A: [M,K] row-major, B: [N,K] row-major. BM=BN=128, BK=32, 3-stage cp.async ring.
// 128 threads (4 warps, 2x2 grid of 64x64 warp tiles), 2 CTAs/SM (occ 3 spills: R14).
// Term-major MMA order. EPI 1: hi/lo bf16 split + bias. EPI 2: fp32 + bias + rs*b2.
// EPI 3: fp16 SINGLE out (Chi as __half*).
#define NST   3
#define TILEB (128 * 32 * 2)            // 8 KB per sub-tile

template<int EPI, bool FP16, int TERMS>
__global__ __launch_bounds__(128, 2)
void hmma_gemm(const __nv_bfloat16* __restrict__ Ah, const __nv_bfloat16* __restrict__ Al,
               const __nv_bfloat16* __restrict__ Bh, const __nv_bfloat16* __restrict__ Bl,
               const float* __restrict__ bias,
               float* __restrict__ Cf,
               __nv_bfloat16* __restrict__ Chi, __nv_bfloat16* __restrict__ Clo,
               const float* __restrict__ rs, const float* __restrict__ b2,
               int N, int K, size_t sA, size_t sB, size_t sC)
{
    constexpr uint32_t NTILES = (TERMS == 3) ? 4 : 2;
    constexpr uint32_t BOFF   = (TERMS == 1) ? TILEB : 2 * TILEB;  // B_h tile offset
    constexpr uint32_t STG = NTILES * TILEB;
    extern __shared__ char smem[];
    const uint32_t sb = smem_u32(smem);
    const int tid  = threadIdx.x;
    const int lane = tid & 31, wid = tid >> 5;
    const int wr = wid >> 1, wc = wid & 1;       // 2 x 2 warp grid
    const int mr = wr * 64, ncol = wc * 64;      // warp tile 64 x 64
    const int brow = blockIdx.y * 128, bcol = blockIdx.x * 128, bz = blockIdx.z;

    const __nv_bfloat16* pAh = Ah + (size_t)bz * sA + (size_t)brow * K;
    const __nv_bfloat16* pAl = (TERMS >= 2) ? Al + (size_t)bz * sA + (size_t)brow * K : nullptr;
    const __nv_bfloat16* pBh = Bh + (size_t)bz * sB + (size_t)bcol * K;
    const __nv_bfloat16* pBl = (TERMS == 3) ? Bl + (size_t)bz * sB + (size_t)bcol * K : nullptr;

    auto ld_stage = [&](int chunk, int slot) {
        const uint32_t st = sb + (uint32_t)slot * STG;
        #pragma unroll
        for (int i = 0; i < 4; i++) {
            int idx = tid + i * 128;
            int r = idx >> 2, cc = idx & 3;
            uint32_t sw = swz64((uint32_t)r * 64 + cc * 16);
            size_t g = (size_t)r * K + (size_t)chunk * 32 + cc * 8;
            cpasync16(st + sw, pAh + g);
            if constexpr (TERMS >= 2) cpasync16(st + TILEB + sw, pAl + g);
            cpasync16(st + BOFF + sw, pBh + g);
            if constexpr (TERMS == 3) cpasync16(st + 3 * TILEB + sw, pBl + g);
        }
        cp_commit();
    };

    float acc[4][8][4];
    #pragma unroll
    for (int a = 0; a < 4; a++)
        #pragma unroll
        for (int b = 0; b < 8; b++)
            #pragma unroll
            for (int c = 0; c < 4; c++) acc[a][b][c] = 0.f;

    const int KCH = K >> 5;
    ld_stage(0, 0);
    ld_stage(1, 1);

    const int lm = lane >> 3, lr = lane & 7;
    const uint32_t a_row  = (uint32_t)(mr + ((lm & 1) << 3) + lr);
    const uint32_t a_koff = (uint32_t)((lm >> 1) << 3);
    const uint32_t b_row  = (uint32_t)(ncol + ((lm & 2) ? 8 : 0) + lr);
    const uint32_t b_koff = (uint32_t)((lm & 1) << 3);

    int csl = 0, lsl = 2;   // compute slot, load slot
    for (int c = 0; c < KCH; ++c) {
        cp_wait1();
        __syncthreads();
        if (c + 2 < KCH) {
            ld_stage(c + 2, lsl);
            lsl = (lsl == NST - 1) ? 0 : lsl + 1;
        } else {
            cp_commit();
        }
        const uint32_t st = sb + (uint32_t)csl * STG;
        csl = (csl == NST - 1) ? 0 : csl + 1;
        #pragma unroll
        for (int ks = 0; ks < 2; ++ks) {
            uint32_t aH[4][4], aL[4][4], bH[4][4], bL[4][4];
            #pragma unroll
            for (int mt = 0; mt < 4; ++mt) {
                uint32_t sw = swz64((a_row + mt * 16) * 64 + (ks * 16 + a_koff) * 2);
                ldm4(aH[mt], st + sw);
                if constexpr (TERMS >= 2) ldm4(aL[mt], st + TILEB + sw);
            }
            #pragma unroll
            for (int np = 0; np < 4; ++np) {
                uint32_t sw = swz64((b_row + np * 16) * 64 + (ks * 16 + b_koff) * 2);
                ldm4(bH[np], st + BOFF + sw);
                if constexpr (TERMS == 3) ldm4(bL[np], st + 3 * TILEB + sw);
            }
            #pragma unroll
            for (int mt = 0; mt < 4; ++mt)
                #pragma unroll
                for (int np = 0; np < 4; ++np)
                    #pragma unroll
                    for (int sub = 0; sub < 2; ++sub)
                        mma16816t<FP16>(acc[mt][np * 2 + sub], aH[mt], &bH[np][sub * 2]);
            if constexpr (TERMS == 3) {
                #pragma unroll
                for (int mt = 0; mt < 4; ++mt)
                    #pragma unroll
                    for (int np = 0; np < 4; ++np)
                        #pragma unroll
                        for (int sub = 0; sub < 2; ++sub)
                            mma16816t<FP16>(acc[mt][np * 2 + sub], aH[mt], &bL[np][sub * 2]);
                #pragma unroll
                for (int mt = 0; mt < 4; ++mt)
                    #pragma unroll
                    for (int np = 0; np < 4; ++np)
                        #pragma unroll
                        for (int sub = 0; sub < 2; ++sub)
                            mma16816t<FP16>(acc[mt][np * 2 + sub], aL[mt], &bH[np][sub * 2]);
            }
        }
    }

    // ---------------- epilogue ----------------
    const int rq = lane >> 2;          // 0..7
    const int cq = (lane & 3) * 2;     // 0,2,4,6
    float bv[8][2], b2v[8][2];
    #pragma unroll
    for (int nt = 0; nt < 8; ++nt) {
        int col = bcol + ncol + nt * 8 + cq;
        bv[nt][0] = bias ? bias[col]     : 0.f;
        bv[nt][1] = bias ? bias[col + 1] : 0.f;
        if (EPI == 2) { b2v[nt][0] = b2[col]; b2v[nt][1] = b2[col + 1]; }
    }
    #pragma unroll
    for (int mt = 0; mt < 4; ++mt) {
        #pragma unroll
        for (int half_ = 0; half_ < 2; ++half_) {
            int row = brow + mr + mt * 16 + half_ * 8 + rq;
            float rv = (EPI == 2) ? rs[row] : 0.f;
            #pragma unroll
            for (int nt = 0; nt < 8; ++nt) {
                int col = bcol + ncol + nt * 8 + cq;
                float v0 = acc[mt][nt][half_ * 2 + 0] + bv[nt][0];
                float v1 = acc[mt][nt][half_ * 2 + 1] + bv[nt][1];
                if (EPI == 2) { v0 += rv * b2v[nt][0]; v1 += rv * b2v[nt][1]; }
                size_t idx = (size_t)bz * sC + (size_t)row * N + col;
                if constexpr (EPI == 2) {
                    *(float2*)&Cf[idx] = make_float2(v0, v1);
                } else if constexpr (EPI == 1) {
                    __nv_bfloat16 h0 = __float2bfloat16(v0), h1 = __float2bfloat16(v1);
                    __nv_bfloat16 l0 = __float2bfloat16(v0 - __bfloat162float(h0));
                    __nv_bfloat16 l1 = __float2bfloat16(v1 - __bfloat162float(h1));
                    *(uint32_t*)&Chi[idx] = pack_bf2(h0, h1);
                    *(uint32_t*)&Clo[idx] = pack_bf2(l0, l1);
                } else {  // EPI == 3: fp16 single out
                    __half h0 = __float2half_rn(v0), h1 = __float2half_rn(v1);
                    *(uint32_t*)&((__half*)Chi)[idx] = pack_hf2(h0, h1);
                }
            }
        }
    }
}

// ---------------- fused QK^T + softmax + mask kernel ----------------
// S = q @ k^T (3-term bf16) with the FULL row (N=256) in one CTA, then in-register
// softmax + mask (exp computed ONCE, stored in acc), writing betaF (fp32 d_out),
// beta fp16, and masked rowsum.
// 256 threads = 8 warps, 2x4 grid of 64x64 warp tiles. Block tile 128 x 256. K=512.
#define G4_ATILE (128 * 32 * 2)          // 8 KB
#define G4_BTILE (256 * 32 * 2)          // 16 KB
#define G4_STG   (2 * G4_ATILE + 2 * G4_BTILE)   // 48 KB
#define G4_SMEM  (NST * G4_STG)          // 144 KB

__global__ __launch_bounds__(256, 1)
void qk_softmax_kernel(const __nv_bfloat16* __restrict__ qh, const __nv_bfloat16* __restrict__ ql,
                       const __nv_bfloat16* __restrict__ kh, const __nv_bfloat16* __restrict__ kl,
                       const float* __restrict__ masks,
                       float* __restrict__ betaF, __half* __restrict__ bt16,
                       float* __restrict__ rowsum)
{
    extern __shared__ char smem[];
    __shared__ float red[128][4];
    const uint32_t sb = smem_u32(smem);
    const int tid  = threadIdx.x;
    const int lane = tid & 31, wid = tid >> 5;
    const int wr = wid >> 2, wc = wid & 3;       // 2 x 4 warp grid
    const int mr = wr * 64, ncol = wc * 64;      // warp tile 64 x 64
    const int brow = blockIdx.y * 128, bz = blockIdx.z;

    const __nv_bfloat16* pAh = qh + (size_t)(bz * HW_ + brow) * FQK;
    const __nv_bfloat16* pAl = ql + (size_t)(bz * HW_ + brow) * FQK;
    const __nv_bfloat16* pBh = kh + (size_t)(bz * NTOK) * FQK;
    const __nv_bfloat16* pBl = kl + (size_t)(bz * NTOK) * FQK;

    auto ld_stage = [&](int chunk, int slot) {
        const uint32_t st = sb + (uint32_t)slot * G4_STG;
        #pragma unroll
        for (int i = 0; i < 2; i++) {            // A: 128 rows -> 512 lines / 256 thr
            int idx = tid + i * 256;
            int r = idx >> 2, cc = idx & 3;
            uint32_t sw = swz64((uint32_t)r * 64 + cc * 16);
            size_t g = (size_t)r * FQK + (size_t)chunk * 32 + cc * 8;
            cpasync16(st + sw,            pAh + g);
            cpasync16(st + G4_ATILE + sw, pAl + g);
        }
        #pragma unroll
        for (int i = 0; i < 4; i++) {            // B: 256 rows -> 1024 lines / 256 thr
            int idx = tid + i * 256;
            int r = idx >> 2, cc = idx & 3;
            uint32_t sw = swz64((uint32_t)r * 64 + cc * 16);
            size_t g = (size_t)r * FQK + (size_t)chunk * 32 + cc * 8;
            cpasync16(st + 2 * G4_ATILE + sw,            pBh + g);
            cpasync16(st + 2 * G4_ATILE + G4_BTILE + sw, pBl + g);
        }
        cp_commit();
    };

    float acc[4][8][4];
    #pragma unroll
    for (int a = 0; a < 4; a++)
        #pragma unroll
        for (int b = 0; b < 8; b++)
            #pragma unroll
            for (int c = 0; c < 4; c++) acc[a][b][c] = 0.f;

    const int KCH = FQK >> 5;   // 16
    ld_stage(0, 0);
    ld_stage(1, 1);

    const int lm = lane >> 3, lr = lane & 7;
    const uint32_t a_row  = (uint32_t)(mr + ((lm & 1) << 3) + lr);
    const uint32_t a_koff = (uint32_t)((lm >> 1) << 3);
    const uint32_t b_row  = (uint32_t)(ncol + ((lm & 2) ? 8 : 0) + lr);
    const uint32_t b_koff = (uint32_t)((lm & 1) << 3);

    int csl = 0, lsl = 2;
    for (int c = 0; c < KCH; ++c) {
        cp_wait1();
        __syncthreads();
        if (c + 2 < KCH) {
            ld_stage(c + 2, lsl);
            lsl = (lsl == NST - 1) ? 0 : lsl + 1;
        } else {
            cp_commit();
        }
        const uint32_t st = sb + (uint32_t)csl * G4_STG;
        csl = (csl == NST - 1) ? 0 : csl + 1;
        #pragma unroll
        for (int ks = 0; ks < 2; ++ks) {
            uint32_t aH[4][4], aL[4][4], bH[4][4], bL[4][4];
            #pragma unroll
            for (int mt = 0; mt < 4; ++mt) {
                uint32_t sw = swz64((a_row + mt * 16) * 64 + (ks * 16 + a_koff) * 2);
                ldm4(aH[mt], st + sw);
                ldm4(aL[mt], st + G4_ATILE + sw);
            }
            #pragma unroll
            for (int np = 0; np < 4; ++np) {
                uint32_t sw = swz64((b_row + np * 16) * 64 + (ks * 16 + b_koff) * 2);
                ldm4(bH[np], st + 2 * G4_ATILE + sw);
                ldm4(bL[np], st + 2 * G4_ATILE + G4_BTILE + sw);
            }
            #pragma unroll
            for (int mt = 0; mt < 4; ++mt)
                #pragma unroll
                for (int np = 0; np < 4; ++np)
                    #pragma unroll
                    for (int sub = 0; sub < 2; ++sub)
                        mma16816t<false>(acc[mt][np * 2 + sub], aH[mt], &bH[np][sub * 2]);
            #pragma unroll
            for (int mt = 0; mt < 4; ++mt)
                #pragma unroll
                for (int np = 0; np < 4; ++np)
                    #pragma unroll
                    for (int sub = 0; sub < 2; ++sub)
                        mma16816t<false>(acc[mt][np * 2 + sub], aH[mt], &bL[np][sub * 2]);
            #pragma unroll
            for (int mt = 0; mt < 4; ++mt)
                #pragma unroll
                for (int np = 0; np < 4; ++np)
                    #pragma unroll
                    for (int sub = 0; sub < 2; ++sub)
                        mma16816t<false>(acc[mt][np * 2 + sub], aL[mt], &bH[np][sub * 2]);
        }
    }

    // ---------------- fused softmax epilogue (exp computed once) ----------------
    const int rq = lane >> 2;          // 0..7
    const int cq = (lane & 3) * 2;     // 0,2,4,6
    const bool qlead = ((lane & 3) == 0);

    // 1) row max: per-thread over 16 cols, quad-reduce, cross-warp via smem
    float rmax[8];
    #pragma unroll
    for (int mt = 0; mt < 4; ++mt)
        #pragma unroll
        for (int h = 0; h < 2; ++h) {
            float m = -1e30f;
            #pragma unroll
            for (int nt = 0; nt < 8; ++nt) {
                m = fmaxf(m, acc[mt][nt][h * 2 + 0]);
                m = fmaxf(m, acc[mt][nt][h * 2 + 1]);
            }
            m = fmaxf(m, __shfl_xor_sync(0xffffffffu, m, 1));
            m = fmaxf(m, __shfl_xor_sync(0xffffffffu, m, 2));
            if (qlead) red[mr + mt * 16 + h * 8 + rq][wc] = m;
        }
    __syncthreads();
    #pragma unroll
    for (int mt = 0; mt < 4; ++mt)
        #pragma unroll
        for (int h = 0; h < 2; ++h) {
            int r = mr + mt * 16 + h * 8 + rq;
            rmax[mt * 2 + h] = fmaxf(fmaxf(red[r][0], red[r][1]), fmaxf(red[r][2], red[r][3]));
        }
    __syncthreads();

    // 2) transform acc -> exp(acc - rmax) IN PLACE, then row-sum
    float rden[8];
    #pragma unroll
    for (int mt = 0; mt < 4; ++mt)
        #pragma unroll
        for (int h = 0; h < 2; ++h) {
            float s = 0.f;
            const float mx = rmax[mt * 2 + h];
            #pragma unroll
            for (int nt = 0; nt < 8; ++nt) {
                float e0 = __expf(acc[mt][nt][h * 2 + 0] - mx);
                float e1 = __expf(acc[mt][nt][h * 2 + 1] - mx);
                acc[mt][nt][h * 2 + 0] = e0;
                acc[mt][nt][h * 2 + 1] = e1;
                s += e0 + e1;
            }
            s += __shfl_xor_sync(0xffffffffu, s, 1);
            s += __shfl_xor_sync(0xffffffffu, s, 2);
            if (qlead) red[mr + mt * 16 + h * 8 + rq][wc] = s;
        }
    __syncthreads();
    #pragma unroll
    for (int mt = 0; mt < 4; ++mt)
        #pragma unroll
        for (int h = 0; h < 2; ++h) {
            int r = mr + mt * 16 + h * 8 + rq;
            rden[mt * 2 + h] = 1.f / (red[r][0] + red[r][1] + red[r][2] + red[r][3]);
        }
    __syncthreads();

    // 3) write beta (fp32 + fp16) with mask; accumulate masked rowsum
    #pragma unroll
    for (int mt = 0; mt < 4; ++mt)
        #pragma unroll
        for (int h = 0; h < 2; ++h) {
            const int rloc = mr + mt * 16 + h * 8 + rq;
            const size_t grow = (size_t)(bz * HW_ + brow + rloc);
            const float inv = rden[mt * 2 + h];
            float msum = 0.f;
            #pragma unroll
            for (int nt = 0; nt < 8; ++nt) {
                int col = ncol + nt * 8 + cq;
                float m0 = masks[(bz << 8) + col], m1 = masks[(bz << 8) + col + 1];
                float b0 = acc[mt][nt][h * 2 + 0] * inv * m0;
                float b1 = acc[mt][nt][h * 2 + 1] * inv * m1;
                *(float2*)&betaF[(grow << 8) + col] = make_float2(b0, b1);
                *(uint32_t*)&bt16[(grow << 8) + col] =
                    pack_hf2(__float2half_rn(b0), __float2half_rn(b1));
                msum += b0 + b1;
            }
            msum += __shfl_xor_sync(0xffffffffu, msum, 1);
            msum += __shfl_xor_sync(0xffffffffu, msum, 2);
            if (qlead) red[rloc][wc] = msum;
        }
    __syncthreads();
    if (wc == 0 && qlead) {
        #pragma unroll
        for (int mt = 0; mt < 4; ++mt)
            #pragma unroll
            for (int h = 0; h < 2; ++h) {
                const int rloc = mr + mt * 16 + h * 8 + rq;
                rowsum[(size_t)(bz * HW_ + brow + rloc)] =
                    red[rloc][0] + red[rloc][1] + red[rloc][2] + red[rloc][3];
            }
    }
}

// ---------------- host launch ----------------
#define HS3 (NST * 4 * TILEB)   // 98304
#define HS1 (NST * 2 * TILEB)   // 49152

extern "C" void kernel_launch(void* const* d_in, const int* in_sizes, int n_in,
                              void* d_out, int out_size)
{
    (void)in_sizes; (void)n_in; (void)out_size;
    const float* x1    = (const float*)d_in[0];
    const float* x2    = (const float*)d_in[1];
    const float* masks = (const float*)d_in[2];
    const float* Wq    = (const float*)d_in[3];
    const float* bq    = (const float*)d_in[4];
    const float* Wk    = (const float*)d_in[5];
    const float* bk    = (const float*)d_in[6];
    const float* Wv    = (const float*)d_in[7];
    const float* bv    = (const float*)d_in[8];
    const float* Wo    = (const float*)d_in[9];
    const float* bo    = (const float*)d_in[10];

    float* outp  = (float*)d_out;
    float* betaF = (float*)d_out + O_ELEMS;

    __nv_bfloat16 *x1h,*x1l,*x2h,*x2l,*wqh,*wql,*wkh,*wkl,*wvh,*wvl,*woh,*wol;
    __nv_bfloat16 *qh,*ql,*kh,*kl;
    __half *wvot16,*x2t16,*bt16,*bx16;
    float *rowsum, *bvwo;
    cudaGetSymbolAddress((void**)&x1h, g_x1h); cudaGetSymbolAddress((void**)&x1l, g_x1l);
    cudaGetSymbolAddress((void**)&x2h, g_x2h); cudaGetSymbolAddress((void**)&x2l, g_x2l);
    cudaGetSymbolAddress((void**)&wqh, g_wqh); cudaGetSymbolAddress((void**)&wql, g_wql);
    cudaGetSymbolAddress((void**)&wkh, g_wkh); cudaGetSymbolAddress((void**)&wkl, g_wkl);
    cudaGetSymbolAddress((void**)&wvh, g_wvh); cudaGetSymbolAddress((void**)&wvl, g_wvl);
    cudaGetSymbolAddress((void**)&woh, g_woh); cudaGetSymbolAddress((void**)&wol, g_wol);
    cudaGetSymbolAddress((void**)&qh, g_qh);   cudaGetSymbolAddress((void**)&ql, g_ql);
    cudaGetSymbolAddress((void**)&kh, g_kh);   cudaGetSymbolAddress((void**)&kl, g_kl);
    cudaGetSymbolAddress((void**)&wvot16, g_wvot16);
    cudaGetSymbolAddress((void**)&x2t16, g_x2t16);
    cudaGetSymbolAddress((void**)&bt16, g_bt16);
    cudaGetSymbolAddress((void**)&bx16, g_bx16);
    cudaGetSymbolAddress((void**)&rowsum, g_rowsum);
    cudaGetSymbolAddress((void**)&bvwo, g_bvwo);

    cudaFuncSetAttribute((const void*)hmma_gemm<1,false,3>, cudaFuncAttributeMaxDynamicSharedMemorySize, HS3);
    cudaFuncSetAttribute((const void*)hmma_gemm<3,false,3>, cudaFuncAttributeMaxDynamicSharedMemorySize, HS3);
    cudaFuncSetAttribute((const void*)hmma_gemm<3,true,1>,  cudaFuncAttributeMaxDynamicSharedMemorySize, HS1);
    cudaFuncSetAttribute((const void*)hmma_gemm<2,true,1>,  cudaFuncAttributeMaxDynamicSharedMemorySize, HS1);
    cudaFuncSetAttribute((const void*)qk_softmax_kernel,    cudaFuncAttributeMaxDynamicSharedMemorySize, G4_SMEM);

    // ---- streams/events: created ONCE, kept alive (inside the harness baseline) ----
    static cudaStream_t s2 = nullptr, s3 = nullptr;
    static cudaEvent_t  e_start = nullptr, e_g2 = nullptr, e_gW = nullptr, e_x2t = nullptr;
    if (s2 == nullptr) {
        cudaStreamCreateWithFlags(&s2, cudaStreamNonBlocking);
        cudaStreamCreateWithFlags(&s3, cudaStreamNonBlocking);
        cudaEventCreateWithFlags(&e_start, cudaEventDisableTiming);
        cudaEventCreateWithFlags(&e_g2,    cudaEventDisableTiming);
        cudaEventCreateWithFlags(&e_gW,    cudaEventDisableTiming);
        cudaEventCreateWithFlags(&e_x2t,   cudaEventDisableTiming);
    }
    cudaStream_t s0 = 0;

    cudaEventRecord(e_start, s0);
    cudaStreamWaitEvent(s2, e_start, 0);
    cudaStreamWaitEvent(s3, e_start, 0);

    // ===== stream s0: x1 -> q chain =====
    {
        int n4 = (M_FLAT * IMG_CH) / 4;
        split_kernel<<<(n4 + 255) / 256, 256, 0, s0>>>(x1, x1h, x1l, n4);
    }
    transpose_split_kernel<<<dim3(FQK/32, IMG_CH/32), dim3(32,8), 0, s0>>>(Wq, wqh, wql, IMG_CH, FQK);
    hmma_gemm<1,false,3><<<dim3(FQK/128, M_FLAT/128, 1), 128, HS3, s0>>>(
        x1h, x1l, wqh, wql, bq, nullptr, qh, ql, nullptr, nullptr,
        FQK, IMG_CH, 0, 0, 0);

    // ===== stream s2: x2 -> k chain; x2^T after the qk gate =====
    {
        int n4 = (M_FLAT * TEXT_CH) / 4;
        split_kernel<<<(n4 + 255) / 256, 256, 0, s2>>>(x2, x2h, x2l, n4);
    }
    transpose_split_kernel<<<dim3(FQK/32, TEXT_CH/32), dim3(32,8), 0, s2>>>(Wk, wkh, wkl, TEXT_CH, FQK);
    hmma_gemm<1,false,3><<<dim3(FQK/128, M_FLAT/128, 1), 128, HS3, s2>>>(
        x2h, x2l, wkh, wkl, bk, nullptr, kh, kl, nullptr, nullptr,
        FQK, TEXT_CH, 0, 0, 0);
    cudaEventRecord(e_g2, s2);              // qk_softmax only needs k (and q)
    transpose_f2h_kernel<<<dim3(TEXT_CH/32, NTOK/32, BATCH), dim3(32,8), 0, s2>>>(
        x2, x2t16, NTOK, TEXT_CH);
    cudaEventRecord(e_x2t, s2);             // g5b additionally needs x2^T

    // ===== stream s3: fused weight Wvo^T (bf16 3-term -> fp16 single) + bias precompute =====
    {
        int n4 = (TEXT_CH * IMG_CH) / 4;
        split_kernel<<<(n4 + 255) / 256, 256, 0, s3>>>(Wv, wvh, wvl, n4);   // PLAIN split [768,1024]
    }
    transpose_split_kernel<<<dim3(IMG_CH/32, IMG_CH/32), dim3(32,8), 0, s3>>>(Wo, woh, wol, IMG_CH, IMG_CH);
    bias_vo_kernel<<<IMG_CH/256, 256, 0, s3>>>(bv, Wo, bvwo);
    // Wvo^T[f,c] = sum_k Wo^T[f,k] * Wv[c,k]  (M=1024, N=768, K=1024), fp16 single out
    hmma_gemm<3,false,3><<<dim3(TEXT_CH/128, IMG_CH/128, 1), 128, HS3, s3>>>(
        woh, wol, wvh, wvl, nullptr, nullptr, (__nv_bfloat16*)wvot16, nullptr, nullptr, nullptr,
        TEXT_CH, IMG_CH, 0, 0, 0);
    cudaEventRecord(e_gW, s3);

    // ===== join on s0: attention chain =====
    cudaStreamWaitEvent(s0, e_g2, 0);
    // fused g4 + softmax: S = q@k^T -> softmax*mask -> betaF (d_out) + beta fp16 + rowsum
    qk_softmax_kernel<<<dim3(1, HW_/128, BATCH), 256, G4_SMEM, s0>>>(
        qh, ql, kh, kl, masks, betaF, bt16, rowsum);
    // g5b: bx2 = beta @ x2 (batched; fp16 1-term) -> fp16 single
    cudaStreamWaitEvent(s0, e_x2t, 0);
    hmma_gemm<3,true,1><<<dim3(TEXT_CH/128, HW_/128, BATCH), 128, HS1, s0>>>(
        (__nv_bfloat16*)bt16, nullptr, (__nv_bfloat16*)x2t16, nullptr,
        nullptr, nullptr, (__nv_bfloat16*)bx16, nullptr, nullptr, nullptr,
        TEXT_CH, NTOK, (size_t)HW_ * NTOK, (size_t)TEXT_CH * NTOK, (size_t)HW_ * TEXT_CH);
    // g6b: out = bx2 @ Wvo^T + rowsum*bvwo + bo (fp16 1-term, M=16384, N=1024, K=768)
    cudaStreamWaitEvent(s0, e_gW, 0);
    hmma_gemm<2,true,1><<<dim3(IMG_CH/128, M_FLAT/128, 1), 128, HS1, s0>>>(
        (__nv_bfloat16*)bx16, nullptr, (__nv_bfloat16*)wvot16, nullptr,
        bo, outp, nullptr, nullptr, rowsum, bvwo,
        IMG_CH, TEXT_CH, 0, 0, 0);
}